// round 11
// baseline (speedup 1.0000x reference)
#include <cuda_runtime.h>
#include <cuda_bf16.h>
#include <math.h>
#include <stdint.h>

#define HH 768
#define LAYERS 10
#define WW 10
#define BB 512
#define G4H 3072
#define TB 5120          // WW*BB
#define KFC1 (WW*HH)     // 7680
#define SPLITK 12

#define KT 32            // K-slab in elements
#define STRIDE 20        // u32 per smem row (16 used + 4 pad; ldmatrix conflict-free)
#define APLANE (128 * STRIDE)          // u32 (A: 128 rows)
#define BPLANE (64 * STRIDE)           // u32 (B: 64 rows)
#define STAGE_U32 (2 * APLANE + 2 * BPLANE)   // 7680 u32 = 30720 B
#define SMEM_BYTES (2 * STAGE_U32 * 4)        // 61440 (2-stage)

#define RECGRID 192      // 48 x 4 CTAs, co-resident at occ 2

typedef __nv_bfloat16 bf16;

// ---------------- scratch (device globals; allocation-free rule) -------------
__device__ bf16  g_xAhi[TB * HH], g_xAlo[TB * HH];
__device__ bf16  g_xBhi[TB * HH], g_xBlo[TB * HH];
__device__ float g_gx[TB * G4H];
__device__ float g_c[BB * HH];
__device__ bf16  g_xcathi[BB * KFC1], g_xcatlo[BB * KFC1];   // also fc0 input temp
__device__ bf16  g_fc0whi[HH * HH],   g_fc0wlo[HH * HH];
__device__ bf16  g_fc1whi[HH * KFC1], g_fc1wlo[HH * KFC1];
__device__ bf16  g_wihhi[LAYERS * G4H * HH], g_wihlo[LAYERS * G4H * HH];
__device__ bf16  g_whhhi[LAYERS * G4H * HH], g_whhlo[LAYERS * G4H * HH];
__device__ float g_bcomb[LAYERS * G4H];
__device__ float g_part[SPLITK * BB * HH];
__device__ int   g_ctr[LAYERS * 8];          // grid barriers (reset every call)

// ---------------- helpers ----------------------------------------------------
__device__ __forceinline__ void split1(float v, bf16& h, bf16& l)
{
    h = __float2bfloat16_rn(v);
    l = __float2bfloat16_rn(v - __bfloat162float(h));
}

__device__ __forceinline__ float sigm(float x) { return 1.0f / (1.0f + expf(-x)); }

__device__ __forceinline__ void cpasync16(void* dst, const void* src)
{
    uint32_t s = (uint32_t)__cvta_generic_to_shared(dst);
    asm volatile("cp.async.cg.shared.global [%0], [%1], 16;\n" :: "r"(s), "l"(src));
}
__device__ __forceinline__ void cp_commit() { asm volatile("cp.async.commit_group;\n"); }

__device__ __forceinline__ void mma_bf16(float* c, const uint32_t* a, const uint32_t* b)
{
    asm volatile(
        "mma.sync.aligned.m16n8k16.row.col.f32.bf16.bf16.f32 "
        "{%0,%1,%2,%3}, {%4,%5,%6,%7}, {%8,%9}, {%0,%1,%2,%3};"
        : "+f"(c[0]), "+f"(c[1]), "+f"(c[2]), "+f"(c[3])
        : "r"(a[0]), "r"(a[1]), "r"(a[2]), "r"(a[3]), "r"(b[0]), "r"(b[1]));
}

__device__ __forceinline__ void ldsm4(uint32_t* r, uint32_t saddr)
{
    asm volatile("ldmatrix.sync.aligned.m8n8.x4.shared.b16 {%0,%1,%2,%3}, [%4];"
                 : "=r"(r[0]), "=r"(r[1]), "=r"(r[2]), "=r"(r[3]) : "r"(saddr));
}

// ================= shared GEMM core pieces (tile 128M x 64N) =================
// loader: per slab 1536 16B-chunks: A planes 2x512, B planes 2x256
#define GEMM_VARS \
    const int tid = threadIdx.x; \
    const int lane = tid & 31; \
    const int wid = tid >> 5; \
    const int wm = wid >> 2; \
    const int wn = wid & 3; \
    const int q = lane >> 2; \
    const int r = lane & 3; \
    const int lrowA = ((lane >> 3) & 1) * 8 + (lane & 7); \
    const int lchA  = (lane >> 4) & 1; \
    const int lrowB = ((lane >> 4) & 1) * 8 + (lane & 7); \
    const int lchB  = (lane >> 3) & 1;

#define GEMM_ISSUE(Ahi_, Alo_, Bhi_, Blo_, Ka_, Kb_, bm_, bn_, k0_, base_) \
    { \
        uint32_t* base = (base_); \
        _Pragma("unroll") \
        for (int i = 0; i < 2; i++) { \
            int f = tid + i * 256; \
            int m = f >> 2, cc = f & 3; \
            size_t ga = (size_t)((bm_) + m) * (Ka_) + (k0_) + cc * 8; \
            int off = m * STRIDE + cc * 4; \
            cpasync16(base + off,          (Ahi_) + ga); \
            cpasync16(base + APLANE + off, (Alo_) + ga); \
        } \
        { \
            int f = tid; \
            int m = f >> 2, cc = f & 3; \
            size_t gb = (size_t)((bn_) + m) * (Kb_) + (k0_) + cc * 8; \
            int off = m * STRIDE + cc * 4; \
            cpasync16(base + 2 * APLANE + off,          (Bhi_) + gb); \
            cpasync16(base + 2 * APLANE + BPLANE + off, (Blo_) + gb); \
        } \
        cp_commit(); \
    }

#define GEMM_COMPUTE(smem_b_, stage_, acc_) \
    { \
        uint32_t Ahb = (smem_b_) + ((stage_) * STAGE_U32) * 4; \
        uint32_t Alb = Ahb + APLANE * 4; \
        uint32_t Bhb = Ahb + 2 * APLANE * 4; \
        uint32_t Blb = Bhb + BPLANE * 4; \
        uint32_t aoff = (uint32_t)((wm * 64 + lrowA) * STRIDE + lchA * 4) * 4; \
        uint32_t boff = (uint32_t)((wn * 16 + lrowB) * STRIDE + lchB * 4) * 4; \
        _Pragma("unroll") \
        for (int k16 = 0; k16 < 2; k16++) { \
            uint32_t kb = (uint32_t)(k16 * 8) * 4; \
            uint32_t bh[2][2], bl[2][2]; \
            { \
                uint32_t bo = boff + kb; \
                uint32_t r4[4]; \
                ldsm4(r4, Bhb + bo); \
                bh[0][0] = r4[0]; bh[0][1] = r4[1]; \
                bh[1][0] = r4[2]; bh[1][1] = r4[3]; \
                ldsm4(r4, Blb + bo); \
                bl[0][0] = r4[0]; bl[0][1] = r4[1]; \
                bl[1][0] = r4[2]; bl[1][1] = r4[3]; \
            } \
            _Pragma("unroll") \
            for (int mi = 0; mi < 4; mi++) { \
                uint32_t ao = aoff + kb + (uint32_t)(mi * 16 * STRIDE) * 4; \
                uint32_t ah[4], al[4]; \
                ldsm4(ah, Ahb + ao); \
                _Pragma("unroll") \
                for (int ni = 0; ni < 2; ni++) { \
                    mma_bf16(acc_[mi][ni], ah, bh[ni]); \
                    mma_bf16(acc_[mi][ni], ah, bl[ni]); \
                } \
                ldsm4(al, Alb + ao); \
                _Pragma("unroll") \
                for (int ni = 0; ni < 2; ni++) \
                    mma_bf16(acc_[mi][ni], al, bh[ni]); \
            } \
        } \
    }

// ---------------- regular GEMM (2-stage, occ 2, tile 128x64) -----------------
// MODE 1: (Chi,Clo) split bf16 = acc + bias                       (fc0)
// MODE 3: rows<BB fused cell first=1 (g = acc + bias); rows>=BB: gx = acc + bias
// MODE 4: raw fp32 partial store (split-K via blockIdx.z)         (fc1)
template <int MODE>
__global__ __launch_bounds__(256, 2) void gemm_bf16(
    const bf16* __restrict__ Ahi, const bf16* __restrict__ Alo,
    const bf16* __restrict__ Bhi, const bf16* __restrict__ Blo,
    const float* __restrict__ bias,
    float* __restrict__ Cf,
    bf16* __restrict__ Chi, bf16* __restrict__ Clo,
    float* __restrict__ cstate,
    int M, int N, int K, int nsplit)
{
    extern __shared__ uint32_t sm[];
    GEMM_VARS
    const int bm = blockIdx.y * 128;
    const int bn = blockIdx.x * 64;
    const uint32_t smem_b = (uint32_t)__cvta_generic_to_shared(sm);

    const int NS = K / KT;
    const int NSLABS = NS / nsplit;
    const int s0 = blockIdx.z * NSLABS;

    float acc[4][2][4];
#pragma unroll
    for (int i = 0; i < 4; i++)
#pragma unroll
        for (int j = 0; j < 2; j++)
#pragma unroll
            for (int v = 0; v < 4; v++) acc[i][j][v] = 0.f;

    GEMM_ISSUE(Ahi, Alo, Bhi, Blo, K, K, bm, bn, s0 * KT, sm);
    if (NSLABS > 1) GEMM_ISSUE(Ahi, Alo, Bhi, Blo, K, K, bm, bn, (s0 + 1) * KT, sm + STAGE_U32)
    else cp_commit();
    for (int s = 0; s < NSLABS; s++) {
        if (s + 1 < NSLABS) asm volatile("cp.async.wait_group 1;\n");
        else                asm volatile("cp.async.wait_group 0;\n");
        __syncthreads();
        GEMM_COMPUTE(smem_b, (s & 1), acc);
        __syncthreads();
        if (s + 2 < NSLABS)
            GEMM_ISSUE(Ahi, Alo, Bhi, Blo, K, K, bm, bn, (s0 + s + 2) * KT, sm + (s & 1) * STAGE_U32);
    }

    // ----------------- epilogue -----------------
#pragma unroll
    for (int mi = 0; mi < 4; mi++) {
#pragma unroll
        for (int ni = 0; ni < 2; ni++) {
            int m0 = bm + wm * 64 + mi * 16 + q;
            int n0 = bn + wn * 16 + ni * 8 + r * 2;
            float* a = acc[mi][ni];

            if (MODE == 1) {
                float bv0 = bias[n0], bv1 = bias[n0 + 1];
                float v00 = a[0] + bv0, v01 = a[1] + bv1;
                float v10 = a[2] + bv0, v11 = a[3] + bv1;
                bf16 h0, l0, h1, l1;
                split1(v00, h0, l0); split1(v01, h1, l1);
                *(__nv_bfloat162*)(Chi + (size_t)m0 * N + n0) = __nv_bfloat162(h0, h1);
                *(__nv_bfloat162*)(Clo + (size_t)m0 * N + n0) = __nv_bfloat162(l0, l1);
                split1(v10, h0, l0); split1(v11, h1, l1);
                *(__nv_bfloat162*)(Chi + (size_t)(m0 + 8) * N + n0) = __nv_bfloat162(h0, h1);
                *(__nv_bfloat162*)(Clo + (size_t)(m0 + 8) * N + n0) = __nv_bfloat162(l0, l1);
            } else if (MODE == 4) {
                float* dst = Cf + ((size_t)blockIdx.z * M + m0) * N + n0;
                dst[0] = a[0]; dst[1] = a[1];
                dst += (size_t)8 * N;
                dst[0] = a[2]; dst[1] = a[3];
            } else {
                float bv0 = bias[n0], bv1 = bias[n0 + 1];
                float a0 = a[0] + bv0, a1 = a[1] + bv1;
                float a2 = a[2] + bv0, a3 = a[3] + bv1;
                if (m0 < BB) {
                    // fused t=0 cell
                    float p0 = __shfl_xor_sync(0xFFFFFFFFu, a0, 1);
                    float p1 = __shfl_xor_sync(0xFFFFFFFFu, a1, 1);
                    float p2 = __shfl_xor_sync(0xFFFFFFFFu, a2, 1);
                    float p3 = __shfl_xor_sync(0xFFFFFFFFu, a3, 1);
                    if ((r & 1) == 0) {
                        int n = n0 >> 2;
#pragma unroll
                        for (int rr = 0; rr < 2; rr++) {
                            int m = m0 + rr * 8;
                            float gi = rr ? a2 : a0;
                            float gg = rr ? p2 : p0;
                            float go = rr ? p3 : p1;
                            float cn = sigm(gi) * tanhf(gg);
                            cstate[(size_t)m * HH + n] = cn;
                            float h = sigm(go) * tanhf(cn);
                            bf16 hh, hl;
                            split1(h, hh, hl);
                            Chi[(size_t)m * HH + n] = hh;
                            Clo[(size_t)m * HH + n] = hl;
                        }
                    }
                } else {
                    float* dst = Cf + (size_t)m0 * N + n0;
                    dst[0] = a0; dst[1] = a1;
                    dst += (size_t)8 * N;
                    dst[0] = a2; dst[1] = a3;
                }
            }
        }
    }
}

// ---------------- persistent recurrent layer (grid 192, occ 2, 2-stage) ------
__global__ __launch_bounds__(256, 2) void rec_layer(
    bf16* __restrict__ oh, bf16* __restrict__ ol,
    const bf16* __restrict__ Bhi, const bf16* __restrict__ Blo,
    const float* __restrict__ gx, float* __restrict__ cstate,
    int* __restrict__ ctr)
{
    extern __shared__ uint32_t sm[];
    GEMM_VARS
    const int bm = blockIdx.y * 128;
    const int bn = blockIdx.x * 64;
    const uint32_t smem_b = (uint32_t)__cvta_generic_to_shared(sm);

    for (int t = 1; t < WW; t++) {
        const bf16* Ahi = oh + (size_t)(t - 1) * BB * HH;
        const bf16* Alo = ol + (size_t)(t - 1) * BB * HH;

        float acc[4][2][4];
#pragma unroll
        for (int i = 0; i < 4; i++)
#pragma unroll
            for (int j = 0; j < 2; j++)
#pragma unroll
                for (int v = 0; v < 4; v++) acc[i][j][v] = 0.f;

        GEMM_ISSUE(Ahi, Alo, Bhi, Blo, HH, HH, bm, bn, 0, sm);
        GEMM_ISSUE(Ahi, Alo, Bhi, Blo, HH, HH, bm, bn, KT, sm + STAGE_U32);
        for (int s = 0; s < 24; s++) {
            if (s + 1 < 24) asm volatile("cp.async.wait_group 1;\n");
            else            asm volatile("cp.async.wait_group 0;\n");
            __syncthreads();
            GEMM_COMPUTE(smem_b, (s & 1), acc);
            __syncthreads();
            if (s + 2 < 24)
                GEMM_ISSUE(Ahi, Alo, Bhi, Blo, HH, HH, bm, bn, (s + 2) * KT, sm + (s & 1) * STAGE_U32);
        }

        // epilogue: fused LSTM cell
        const float* gxt = gx + (size_t)t * BB * G4H;
        bf16* Chi = oh + (size_t)t * BB * HH;
        bf16* Clo = ol + (size_t)t * BB * HH;
#pragma unroll
        for (int mi = 0; mi < 4; mi++) {
#pragma unroll
            for (int ni = 0; ni < 2; ni++) {
                int m0 = bm + wm * 64 + mi * 16 + q;
                int n0 = bn + wn * 16 + ni * 8 + r * 2;
                float* a = acc[mi][ni];
                float2 g0 = *(const float2*)(gxt + (size_t)m0 * G4H + n0);
                float2 g1 = *(const float2*)(gxt + (size_t)(m0 + 8) * G4H + n0);
                float a0 = a[0] + g0.x, a1 = a[1] + g0.y;
                float a2 = a[2] + g1.x, a3 = a[3] + g1.y;
                float p0 = __shfl_xor_sync(0xFFFFFFFFu, a0, 1);
                float p1 = __shfl_xor_sync(0xFFFFFFFFu, a1, 1);
                float p2 = __shfl_xor_sync(0xFFFFFFFFu, a2, 1);
                float p3 = __shfl_xor_sync(0xFFFFFFFFu, a3, 1);
                if ((r & 1) == 0) {
                    int n = n0 >> 2;
#pragma unroll
                    for (int rr = 0; rr < 2; rr++) {
                        int m = m0 + rr * 8;
                        float gi = rr ? a2 : a0;
                        float gf = rr ? a3 : a1;
                        float gg = rr ? p2 : p0;
                        float go = rr ? p3 : p1;
                        float cold = cstate[(size_t)m * HH + n];
                        float cn = sigm(gf) * cold + sigm(gi) * tanhf(gg);
                        cstate[(size_t)m * HH + n] = cn;
                        float h = sigm(go) * tanhf(cn);
                        bf16 hh, hl;
                        split1(h, hh, hl);
                        Chi[(size_t)m * HH + n] = hh;
                        Clo[(size_t)m * HH + n] = hl;
                    }
                }
            }
        }

        // grid barrier (h(t) must be visible before any CTA starts step t+1)
        if (t < WW - 1) {
            __threadfence();
            __syncthreads();
            if (tid == 0) {
                atomicAdd(&ctr[t - 1], 1);
                while (atomicAdd(&ctr[t - 1], 0) < RECGRID) __nanosleep(64);
            }
            __syncthreads();
        }
    }
}

// ---------------- prep (merged): weight splits + permute + bias + ctr reset --
__global__ void prep_all(const float* __restrict__ fc0_w, const float* __restrict__ fc1_w,
                         const float* __restrict__ wih, const float* __restrict__ whh,
                         const float* __restrict__ bih, const float* __restrict__ bhh,
                         bf16* __restrict__ f0h, bf16* __restrict__ f0l,
                         bf16* __restrict__ f1h, bf16* __restrict__ f1l,
                         bf16* __restrict__ ihh, bf16* __restrict__ ihl,
                         bf16* __restrict__ hhh, bf16* __restrict__ hhl,
                         float* __restrict__ bc, int* __restrict__ ctr)
{
    int i = blockIdx.x * blockDim.x + threadIdx.x;
    const int NA = HH * HH;
    const int NB = NA + HH * KFC1;
    const int NP = 2 * LAYERS * G4H * HH;
    if (i < NA) { split1(fc0_w[i], f0h[i], f0l[i]); return; }
    if (i < NB) { int j = i - NA; split1(fc1_w[j], f1h[j], f1l[j]); return; }
    int i2 = i - NB;
    if (i2 < NP) {
        int sel = i2 >= NP / 2;
        int ii = sel ? i2 - NP / 2 : i2;
        int k = ii % HH;
        int j = (ii / HH) % G4H;
        int l = ii / (HH * G4H);
        int n = j >> 2, g = j & 3;
        const float* src = sel ? whh : wih;
        float v = src[(size_t)l * G4H * HH + (size_t)(g * HH + n) * HH + k];
        if (sel) split1(v, hhh[ii], hhl[ii]);
        else     split1(v, ihh[ii], ihl[ii]);
        return;
    }
    int i3 = i2 - NP;
    if (i3 < LAYERS * G4H) {
        int j = i3 % G4H;
        int l = i3 / G4H;
        int n = j >> 2, g = j & 3;
        bc[i3] = bih[l * G4H + g * HH + n] + bhh[l * G4H + g * HH + n];
        return;
    }
    int i4 = i3 - LAYERS * G4H;
    if (i4 < LAYERS * 8) ctr[i4] = 0;
}

// (B,W,H) fp32 -> (W*B, H) split bf16
__global__ void transpose_split(const float* __restrict__ src,
                                bf16* __restrict__ hi, bf16* __restrict__ lo)
{
    int i = blockIdx.x * blockDim.x + threadIdx.x;
    if (i >= TB * HH) return;
    int k = i % HH;
    int row = i / HH;
    int t = row / BB, b = row % BB;
    split1(src[((size_t)b * WW + t) * HH + k], hi[i], lo[i]);
}

// (W,B,H) split -> (B, W*H) split
__global__ void pack_split(const bf16* __restrict__ xhi, const bf16* __restrict__ xlo,
                           bf16* __restrict__ chi, bf16* __restrict__ clo)
{
    int i = blockIdx.x * blockDim.x + threadIdx.x;
    if (i >= BB * KFC1) return;
    int b = i / KFC1;
    int tk = i % KFC1;
    int t = tk / HH, k = tk % HH;
    size_t s = ((size_t)t * BB + b) * HH + k;
    chi[i] = xhi[s];
    clo[i] = xlo[s];
}

__global__ void reduce_fc1(const float* __restrict__ part, const float* __restrict__ b,
                           float* __restrict__ out)
{
    int i = blockIdx.x * blockDim.x + threadIdx.x;
    if (i >= BB * HH) return;
    float s = b[i % HH];
#pragma unroll
    for (int z = 0; z < SPLITK; z++) s += part[(size_t)z * BB * HH + i];
    out[i] = s;
}

// ---------------- host -------------------------------------------------------
extern "C" void kernel_launch(void* const* d_in, const int* in_sizes, int n_in,
                              void* d_out, int out_size)
{
    const float* xpos  = (const float*)d_in[0];
    const float* fc0_w = (const float*)d_in[1];
    const float* fc0_b = (const float*)d_in[2];
    const float* w_ih  = (const float*)d_in[3];
    const float* w_hh  = (const float*)d_in[4];
    const float* b_ih  = (const float*)d_in[5];
    const float* b_hh  = (const float*)d_in[6];
    const float* fc1_w = (const float*)d_in[7];
    const float* fc1_b = (const float*)d_in[8];
    float* out = (float*)d_out;

    bf16 *xAhi, *xAlo, *xBhi, *xBlo, *xcathi, *xcatlo;
    bf16 *fc0whi, *fc0wlo, *fc1whi, *fc1wlo, *wihhi, *wihlo, *whhhi, *whhlo;
    float *gx, *c, *bcomb, *part;
    int* ctr;
    cudaGetSymbolAddress((void**)&xAhi, g_xAhi);
    cudaGetSymbolAddress((void**)&xAlo, g_xAlo);
    cudaGetSymbolAddress((void**)&xBhi, g_xBhi);
    cudaGetSymbolAddress((void**)&xBlo, g_xBlo);
    cudaGetSymbolAddress((void**)&xcathi, g_xcathi);
    cudaGetSymbolAddress((void**)&xcatlo, g_xcatlo);
    cudaGetSymbolAddress((void**)&fc0whi, g_fc0whi);
    cudaGetSymbolAddress((void**)&fc0wlo, g_fc0wlo);
    cudaGetSymbolAddress((void**)&fc1whi, g_fc1whi);
    cudaGetSymbolAddress((void**)&fc1wlo, g_fc1wlo);
    cudaGetSymbolAddress((void**)&wihhi, g_wihhi);
    cudaGetSymbolAddress((void**)&wihlo, g_wihlo);
    cudaGetSymbolAddress((void**)&whhhi, g_whhhi);
    cudaGetSymbolAddress((void**)&whhlo, g_whhlo);
    cudaGetSymbolAddress((void**)&gx,    g_gx);
    cudaGetSymbolAddress((void**)&c,     g_c);
    cudaGetSymbolAddress((void**)&bcomb, g_bcomb);
    cudaGetSymbolAddress((void**)&part,  g_part);
    cudaGetSymbolAddress((void**)&ctr,   g_ctr);

    static bool once = false;
    if (!once) {
        cudaFuncSetAttribute(gemm_bf16<1>, cudaFuncAttributeMaxDynamicSharedMemorySize, SMEM_BYTES);
        cudaFuncSetAttribute(gemm_bf16<3>, cudaFuncAttributeMaxDynamicSharedMemorySize, SMEM_BYTES);
        cudaFuncSetAttribute(gemm_bf16<4>, cudaFuncAttributeMaxDynamicSharedMemorySize, SMEM_BYTES);
        cudaFuncSetAttribute(rec_layer,    cudaFuncAttributeMaxDynamicSharedMemorySize, SMEM_BYTES);
        once = true;
    }

    const int EL = 256;

    // launch 0: input transpose/split
    transpose_split<<<(TB * HH + EL - 1) / EL, EL>>>(xpos, xcathi, xcatlo);

    // launch 1: merged prep (weights, biases, barrier-counter reset)
    {
        int n = HH * HH + HH * KFC1 + 2 * LAYERS * G4H * HH + LAYERS * G4H + LAYERS * 8;
        prep_all<<<(n + EL - 1) / EL, EL>>>(fc0_w, fc1_w, w_ih, w_hh, b_ih, b_hh,
                                            fc0whi, fc0wlo, fc1whi, fc1wlo,
                                            wihhi, wihlo, whhhi, whhlo, bcomb, ctr);
    }

    // launch 2: fc0 (split store)
    gemm_bf16<1><<<dim3(HH / 64, TB / 128, 1), 256, SMEM_BYTES>>>(
        xcathi, xcatlo, fc0whi, fc0wlo, fc0_b,
        nullptr, xAhi, xAlo, nullptr, TB, HH, HH, 1);

    for (int l = 0; l < LAYERS; l++) {
        bf16* ih = (l & 1) ? xBhi : xAhi;
        bf16* il = (l & 1) ? xBlo : xAlo;
        bf16* oh = (l & 1) ? xAhi : xBhi;
        bf16* ol = (l & 1) ? xAlo : xBlo;
        const bf16* wihh = wihhi + (size_t)l * G4H * HH;
        const bf16* wihl = wihlo + (size_t)l * G4H * HH;
        const bf16* whhh = whhhi + (size_t)l * G4H * HH;
        const bf16* whhl = whhlo + (size_t)l * G4H * HH;
        const float* bl_ = bcomb + (size_t)l * G4H;

        // input GEMM: t=0 rows -> fused cell into oh/ol; t>0 rows -> gx (+bias)
        gemm_bf16<3><<<dim3(G4H / 64, TB / 128, 1), 256, SMEM_BYTES>>>(
            ih, il, wihh, wihl, bl_,
            gx, oh, ol, c, TB, G4H, HH, 1);

        // persistent recurrent: steps 1..9 with internal grid barriers
        rec_layer<<<dim3(G4H / 64, BB / 128, 1), 256, SMEM_BYTES>>>(
            oh, ol, whhh, whhl, gx, c, ctr + l * 8);
    }

    // final activations in xA (10 layers, even count)
    pack_split<<<(BB * KFC1 + EL - 1) / EL, EL>>>(xAhi, xAlo, xcathi, xcatlo);

    // fc1 split-K partials + reduce
    gemm_bf16<4><<<dim3(HH / 64, BB / 128, SPLITK), 256, SMEM_BYTES>>>(
        xcathi, xcatlo, fc1whi, fc1wlo, nullptr,
        part, nullptr, nullptr, nullptr, BB, HH, KFC1, SPLITK);
    reduce_fc1<<<(BB * HH + EL - 1) / EL, EL>>>(part, fc1_b, out);
}

// round 12
// speedup vs baseline: 1.0423x; 1.0423x over previous
#include <cuda_runtime.h>
#include <cuda_bf16.h>
#include <math.h>
#include <stdint.h>

#define HH 768
#define LAYERS 10
#define WW 10
#define BB 512
#define G4H 3072
#define TB 5120          // WW*BB
#define KFC1 (WW*HH)     // 7680
#define SPLITK 12

#define KT 32            // K-slab in elements
#define STRIDE 20        // u32 per smem row (16 used + 4 pad; ldmatrix conflict-free)
#define PLANE (128 * STRIDE)               // u32 per 128-row plane
#define SMEM_BYTES (2 * 4 * PLANE * 4)     // 81920 (128x128 GEMM, 2-stage)

#define BPLANE (64 * STRIDE)               // u32 per 64-row plane
#define RSTAGE_U32 (2 * PLANE + 2 * BPLANE)   // 7680 u32 = 30720 B
#define RSMEM_BYTES (3 * RSTAGE_U32 * 4)      // 92160 (rec, 3-stage)

#define RECGRID 192      // 48 x 4 CTAs, co-resident at occ 2

typedef __nv_bfloat16 bf16;

// ---------------- scratch (device globals; allocation-free rule) -------------
__device__ bf16  g_xAhi[TB * HH], g_xAlo[TB * HH];
__device__ bf16  g_xBhi[TB * HH], g_xBlo[TB * HH];
__device__ float g_gx[TB * G4H];
__device__ float g_c[BB * HH];
__device__ bf16  g_xcathi[BB * KFC1], g_xcatlo[BB * KFC1];   // also fc0 input temp
__device__ bf16  g_fc0whi[HH * HH],   g_fc0wlo[HH * HH];
__device__ bf16  g_fc1whi[HH * KFC1], g_fc1wlo[HH * KFC1];
__device__ bf16  g_wihhi[LAYERS * G4H * HH], g_wihlo[LAYERS * G4H * HH];
__device__ bf16  g_whhhi[LAYERS * G4H * HH], g_whhlo[LAYERS * G4H * HH];
__device__ float g_bcomb[LAYERS * G4H];
__device__ float g_part[SPLITK * BB * HH];
__device__ int   g_ctr[LAYERS * 8];          // grid barriers (reset every call)

// ---------------- helpers ----------------------------------------------------
__device__ __forceinline__ void split1(float v, bf16& h, bf16& l)
{
    h = __float2bfloat16_rn(v);
    l = __float2bfloat16_rn(v - __bfloat162float(h));
}

__device__ __forceinline__ float sigm(float x) { return 1.0f / (1.0f + expf(-x)); }

__device__ __forceinline__ void cpasync16(void* dst, const void* src)
{
    uint32_t s = (uint32_t)__cvta_generic_to_shared(dst);
    asm volatile("cp.async.cg.shared.global [%0], [%1], 16;\n" :: "r"(s), "l"(src));
}
__device__ __forceinline__ void cp_commit() { asm volatile("cp.async.commit_group;\n"); }

__device__ __forceinline__ void mma_bf16(float* c, const uint32_t* a, const uint32_t* b)
{
    asm volatile(
        "mma.sync.aligned.m16n8k16.row.col.f32.bf16.bf16.f32 "
        "{%0,%1,%2,%3}, {%4,%5,%6,%7}, {%8,%9}, {%0,%1,%2,%3};"
        : "+f"(c[0]), "+f"(c[1]), "+f"(c[2]), "+f"(c[3])
        : "r"(a[0]), "r"(a[1]), "r"(a[2]), "r"(a[3]), "r"(b[0]), "r"(b[1]));
}

__device__ __forceinline__ void ldsm4(uint32_t* r, uint32_t saddr)
{
    asm volatile("ldmatrix.sync.aligned.m8n8.x4.shared.b16 {%0,%1,%2,%3}, [%4];"
                 : "=r"(r[0]), "=r"(r[1]), "=r"(r[2]), "=r"(r[3]) : "r"(saddr));
}

// ---------------- regular GEMM (128x128 tile, 2-stage, occ 2) ----------------
// MODE 1: (Chi,Clo) split bf16 = acc + bias                       (fc0)
// MODE 3: rows<BB fused cell first=1 (g = acc + bias); rows>=BB: gx = acc + bias
// MODE 4: raw fp32 partial store (split-K via blockIdx.z)         (fc1)
template <int MODE>
__global__ __launch_bounds__(256, 2) void gemm_bf16(
    const bf16* __restrict__ Ahi, const bf16* __restrict__ Alo,
    const bf16* __restrict__ Bhi, const bf16* __restrict__ Blo,
    const float* __restrict__ bias,
    float* __restrict__ Cf,
    bf16* __restrict__ Chi, bf16* __restrict__ Clo,
    float* __restrict__ cstate,
    int M, int N, int K, int nsplit)
{
    extern __shared__ uint32_t sm[];
    const int tid = threadIdx.x;
    const int lane = tid & 31;
    const int wid = tid >> 5;
    const int wm = wid >> 2;          // 0..1
    const int wn = wid & 3;           // 0..3
    const int bm = blockIdx.y * 128;
    const int bn = blockIdx.x * 128;
    const int q = lane >> 2;
    const int r = lane & 3;

    const int NS = K / KT;
    const int NSLABS = NS / nsplit;
    const int s0 = blockIdx.z * NSLABS;

    const int lrowA = ((lane >> 3) & 1) * 8 + (lane & 7);
    const int lchA  = (lane >> 4) & 1;
    const int lrowB = ((lane >> 4) & 1) * 8 + (lane & 7);
    const int lchB  = (lane >> 3) & 1;
    const uint32_t smem_b = (uint32_t)__cvta_generic_to_shared(sm);

    float acc[4][4][4];
#pragma unroll
    for (int i = 0; i < 4; i++)
#pragma unroll
        for (int j = 0; j < 4; j++)
#pragma unroll
            for (int v = 0; v < 4; v++) acc[i][j][v] = 0.f;

    auto issue = [&](int slab, int stage) {
        int k0 = slab * KT;
        uint32_t* base = sm + stage * 4 * PLANE;
#pragma unroll
        for (int i = 0; i < 2; i++) {
            int f = tid + i * 256;
            int m = f >> 2, cc = f & 3;
            size_t ga = (size_t)(bm + m) * K + k0 + cc * 8;
            size_t gb = (size_t)(bn + m) * K + k0 + cc * 8;
            int off = m * STRIDE + cc * 4;
            cpasync16(base + 0 * PLANE + off, Ahi + ga);
            cpasync16(base + 1 * PLANE + off, Alo + ga);
            cpasync16(base + 2 * PLANE + off, Bhi + gb);
            cpasync16(base + 3 * PLANE + off, Blo + gb);
        }
        cp_commit();
    };

    auto compute = [&](int stage) {
        uint32_t Ahb = smem_b + (stage * 4 + 0) * PLANE * 4;
        uint32_t Alb = smem_b + (stage * 4 + 1) * PLANE * 4;
        uint32_t Bhb = smem_b + (stage * 4 + 2) * PLANE * 4;
        uint32_t Blb = smem_b + (stage * 4 + 3) * PLANE * 4;
        uint32_t aoff = (uint32_t)((wm * 64 + lrowA) * STRIDE + lchA * 4) * 4;
        uint32_t boff = (uint32_t)((wn * 32 + lrowB) * STRIDE + lchB * 4) * 4;
#pragma unroll
        for (int k16 = 0; k16 < 2; k16++) {
            uint32_t kb = (uint32_t)(k16 * 8) * 4;
            uint32_t bh[4][2], bl[4][2];
#pragma unroll
            for (int p = 0; p < 2; p++) {
                uint32_t bo = boff + kb + (uint32_t)(p * 16 * STRIDE) * 4;
                uint32_t r4[4];
                ldsm4(r4, Bhb + bo);
                bh[p * 2][0] = r4[0]; bh[p * 2][1] = r4[1];
                bh[p * 2 + 1][0] = r4[2]; bh[p * 2 + 1][1] = r4[3];
                ldsm4(r4, Blb + bo);
                bl[p * 2][0] = r4[0]; bl[p * 2][1] = r4[1];
                bl[p * 2 + 1][0] = r4[2]; bl[p * 2 + 1][1] = r4[3];
            }
#pragma unroll
            for (int mi = 0; mi < 4; mi++) {
                uint32_t ao = aoff + kb + (uint32_t)(mi * 16 * STRIDE) * 4;
                uint32_t ah[4], al[4];
                ldsm4(ah, Ahb + ao);
#pragma unroll
                for (int ni = 0; ni < 4; ni++) {
                    mma_bf16(acc[mi][ni], ah, bh[ni]);
                    mma_bf16(acc[mi][ni], ah, bl[ni]);
                }
                ldsm4(al, Alb + ao);
#pragma unroll
                for (int ni = 0; ni < 4; ni++)
                    mma_bf16(acc[mi][ni], al, bh[ni]);
            }
        }
    };

    issue(s0, 0);
    if (NSLABS > 1) issue(s0 + 1, 1); else cp_commit();
    for (int s = 0; s < NSLABS; s++) {
        if (s + 1 < NSLABS) asm volatile("cp.async.wait_group 1;\n");
        else                asm volatile("cp.async.wait_group 0;\n");
        __syncthreads();
        compute(s & 1);
        __syncthreads();
        if (s + 2 < NSLABS) issue(s0 + s + 2, s & 1);
    }

    // ----------------- epilogue -----------------
#pragma unroll
    for (int mi = 0; mi < 4; mi++) {
#pragma unroll
        for (int ni = 0; ni < 4; ni++) {
            int m0 = bm + wm * 64 + mi * 16 + q;
            int n0 = bn + wn * 32 + ni * 8 + r * 2;
            float* a = acc[mi][ni];

            if (MODE == 1) {
                float bv0 = bias[n0], bv1 = bias[n0 + 1];
                float v00 = a[0] + bv0, v01 = a[1] + bv1;
                float v10 = a[2] + bv0, v11 = a[3] + bv1;
                bf16 h0, l0, h1, l1;
                split1(v00, h0, l0); split1(v01, h1, l1);
                *(__nv_bfloat162*)(Chi + (size_t)m0 * N + n0) = __nv_bfloat162(h0, h1);
                *(__nv_bfloat162*)(Clo + (size_t)m0 * N + n0) = __nv_bfloat162(l0, l1);
                split1(v10, h0, l0); split1(v11, h1, l1);
                *(__nv_bfloat162*)(Chi + (size_t)(m0 + 8) * N + n0) = __nv_bfloat162(h0, h1);
                *(__nv_bfloat162*)(Clo + (size_t)(m0 + 8) * N + n0) = __nv_bfloat162(l0, l1);
            } else if (MODE == 4) {
                float* dst = Cf + ((size_t)blockIdx.z * M + m0) * N + n0;
                dst[0] = a[0]; dst[1] = a[1];
                dst += (size_t)8 * N;
                dst[0] = a[2]; dst[1] = a[3];
            } else {
                float bv0 = bias[n0], bv1 = bias[n0 + 1];
                float a0 = a[0] + bv0, a1 = a[1] + bv1;
                float a2 = a[2] + bv0, a3 = a[3] + bv1;
                if (m0 < BB) {
                    // fused t=0 cell
                    float p0 = __shfl_xor_sync(0xFFFFFFFFu, a0, 1);
                    float p1 = __shfl_xor_sync(0xFFFFFFFFu, a1, 1);
                    float p2 = __shfl_xor_sync(0xFFFFFFFFu, a2, 1);
                    float p3 = __shfl_xor_sync(0xFFFFFFFFu, a3, 1);
                    if ((r & 1) == 0) {
                        int n = n0 >> 2;
#pragma unroll
                        for (int rr = 0; rr < 2; rr++) {
                            int m = m0 + rr * 8;
                            float gi = rr ? a2 : a0;
                            float gg = rr ? p2 : p0;
                            float go = rr ? p3 : p1;
                            float cn = sigm(gi) * tanhf(gg);
                            cstate[(size_t)m * HH + n] = cn;
                            float h = sigm(go) * tanhf(cn);
                            bf16 hh, hl;
                            split1(h, hh, hl);
                            Chi[(size_t)m * HH + n] = hh;
                            Clo[(size_t)m * HH + n] = hl;
                        }
                    }
                } else {
                    float* dst = Cf + (size_t)m0 * N + n0;
                    dst[0] = a0; dst[1] = a1;
                    dst += (size_t)8 * N;
                    dst[0] = a2; dst[1] = a3;
                }
            }
        }
    }
}

// ------- persistent recurrent layer (128x64 tile, grid 192, occ 2, 3-stage, 1 sync/slab)
__global__ __launch_bounds__(256, 2) void rec_layer(
    bf16* __restrict__ oh, bf16* __restrict__ ol,
    const bf16* __restrict__ Bhi, const bf16* __restrict__ Blo,
    const float* __restrict__ gx, float* __restrict__ cstate,
    int* __restrict__ ctr)
{
    extern __shared__ uint32_t sm[];
    const int tid = threadIdx.x;
    const int lane = tid & 31;
    const int wid = tid >> 5;
    const int wm = wid >> 2;          // 0..1 (64 rows each)
    const int wn = wid & 3;           // 0..3 (16 cols each)
    const int bm = blockIdx.y * 128;
    const int bn = blockIdx.x * 64;
    const int q = lane >> 2;
    const int r = lane & 3;

    const int lrowA = ((lane >> 3) & 1) * 8 + (lane & 7);
    const int lchA  = (lane >> 4) & 1;
    const int lrowB = ((lane >> 4) & 1) * 8 + (lane & 7);
    const int lchB  = (lane >> 3) & 1;
    const uint32_t smem_b = (uint32_t)__cvta_generic_to_shared(sm);

    for (int t = 1; t < WW; t++) {
        const bf16* Ahi = oh + (size_t)(t - 1) * BB * HH;
        const bf16* Alo = ol + (size_t)(t - 1) * BB * HH;

        float acc[4][2][4];
#pragma unroll
        for (int i = 0; i < 4; i++)
#pragma unroll
            for (int j = 0; j < 2; j++)
#pragma unroll
                for (int v = 0; v < 4; v++) acc[i][j][v] = 0.f;

        auto issue = [&](int slab, int slot) {
            int k0 = slab * KT;
            uint32_t* base = sm + slot * RSTAGE_U32;
#pragma unroll
            for (int i = 0; i < 2; i++) {
                int f = tid + i * 256;
                int m = f >> 2, cc = f & 3;
                size_t ga = (size_t)(bm + m) * HH + k0 + cc * 8;
                int off = m * STRIDE + cc * 4;
                cpasync16(base + off,         Ahi + ga);
                cpasync16(base + PLANE + off, Alo + ga);
            }
            {
                int m = tid >> 2, cc = tid & 3;
                size_t gb = (size_t)(bn + m) * HH + k0 + cc * 8;
                int off = m * STRIDE + cc * 4;
                cpasync16(base + 2 * PLANE + off,          Bhi + gb);
                cpasync16(base + 2 * PLANE + BPLANE + off, Blo + gb);
            }
            cp_commit();
        };

        auto compute = [&](int slot) {
            uint32_t Ahb = smem_b + (slot * RSTAGE_U32) * 4;
            uint32_t Alb = Ahb + PLANE * 4;
            uint32_t Bhb = Ahb + 2 * PLANE * 4;
            uint32_t Blb = Bhb + BPLANE * 4;
            uint32_t aoff = (uint32_t)((wm * 64 + lrowA) * STRIDE + lchA * 4) * 4;
            uint32_t boff = (uint32_t)((wn * 16 + lrowB) * STRIDE + lchB * 4) * 4;
#pragma unroll
            for (int k16 = 0; k16 < 2; k16++) {
                uint32_t kb = (uint32_t)(k16 * 8) * 4;
                uint32_t bh[2][2], bl[2][2];
                {
                    uint32_t bo = boff + kb;
                    uint32_t r4[4];
                    ldsm4(r4, Bhb + bo);
                    bh[0][0] = r4[0]; bh[0][1] = r4[1];
                    bh[1][0] = r4[2]; bh[1][1] = r4[3];
                    ldsm4(r4, Blb + bo);
                    bl[0][0] = r4[0]; bl[0][1] = r4[1];
                    bl[1][0] = r4[2]; bl[1][1] = r4[3];
                }
#pragma unroll
                for (int mi = 0; mi < 4; mi++) {
                    uint32_t ao = aoff + kb + (uint32_t)(mi * 16 * STRIDE) * 4;
                    uint32_t ah[4], al[4];
                    ldsm4(ah, Ahb + ao);
#pragma unroll
                    for (int ni = 0; ni < 2; ni++) {
                        mma_bf16(acc[mi][ni], ah, bh[ni]);
                        mma_bf16(acc[mi][ni], ah, bl[ni]);
                    }
                    ldsm4(al, Alb + ao);
#pragma unroll
                    for (int ni = 0; ni < 2; ni++)
                        mma_bf16(acc[mi][ni], al, bh[ni]);
                }
            }
        };

        // 3-stage, one __syncthreads per slab:
        // [wait group s done] -> sync -> issue(s+2 -> slot (s-1)%3) -> compute(s)
        issue(0, 0);
        issue(1, 1);
        for (int s = 0; s < 24; s++) {
            if (s < 23) asm volatile("cp.async.wait_group 1;\n");
            else        asm volatile("cp.async.wait_group 0;\n");
            __syncthreads();
            if (s + 2 < 24) issue(s + 2, (s + 2) % 3);
            compute(s % 3);
        }

        // epilogue: fused LSTM cell
        const float* gxt = gx + (size_t)t * BB * G4H;
        bf16* Chi = oh + (size_t)t * BB * HH;
        bf16* Clo = ol + (size_t)t * BB * HH;
#pragma unroll
        for (int mi = 0; mi < 4; mi++) {
#pragma unroll
            for (int ni = 0; ni < 2; ni++) {
                int m0 = bm + wm * 64 + mi * 16 + q;
                int n0 = bn + wn * 16 + ni * 8 + r * 2;
                float* a = acc[mi][ni];
                float2 g0 = *(const float2*)(gxt + (size_t)m0 * G4H + n0);
                float2 g1 = *(const float2*)(gxt + (size_t)(m0 + 8) * G4H + n0);
                float a0 = a[0] + g0.x, a1 = a[1] + g0.y;
                float a2 = a[2] + g1.x, a3 = a[3] + g1.y;
                float p0 = __shfl_xor_sync(0xFFFFFFFFu, a0, 1);
                float p1 = __shfl_xor_sync(0xFFFFFFFFu, a1, 1);
                float p2 = __shfl_xor_sync(0xFFFFFFFFu, a2, 1);
                float p3 = __shfl_xor_sync(0xFFFFFFFFu, a3, 1);
                if ((r & 1) == 0) {
                    int n = n0 >> 2;
#pragma unroll
                    for (int rr = 0; rr < 2; rr++) {
                        int m = m0 + rr * 8;
                        float gi = rr ? a2 : a0;
                        float gf = rr ? a3 : a1;
                        float gg = rr ? p2 : p0;
                        float go = rr ? p3 : p1;
                        float cold = cstate[(size_t)m * HH + n];
                        float cn = sigm(gf) * cold + sigm(gi) * tanhf(gg);
                        cstate[(size_t)m * HH + n] = cn;
                        float h = sigm(go) * tanhf(cn);
                        bf16 hh, hl;
                        split1(h, hh, hl);
                        Chi[(size_t)m * HH + n] = hh;
                        Clo[(size_t)m * HH + n] = hl;
                    }
                }
            }
        }

        // grid barrier (h(t) must be visible before any CTA starts step t+1)
        if (t < WW - 1) {
            __threadfence();
            __syncthreads();
            if (tid == 0) {
                atomicAdd(&ctr[t - 1], 1);
                while (atomicAdd(&ctr[t - 1], 0) < RECGRID) __nanosleep(64);
            }
            __syncthreads();
        }
    }
}

// ---------------- prep (merged): weight splits + permute + bias + ctr reset --
__global__ void prep_all(const float* __restrict__ fc0_w, const float* __restrict__ fc1_w,
                         const float* __restrict__ wih, const float* __restrict__ whh,
                         const float* __restrict__ bih, const float* __restrict__ bhh,
                         bf16* __restrict__ f0h, bf16* __restrict__ f0l,
                         bf16* __restrict__ f1h, bf16* __restrict__ f1l,
                         bf16* __restrict__ ihh, bf16* __restrict__ ihl,
                         bf16* __restrict__ hhh, bf16* __restrict__ hhl,
                         float* __restrict__ bc, int* __restrict__ ctr)
{
    int i = blockIdx.x * blockDim.x + threadIdx.x;
    const int NA = HH * HH;
    const int NB = NA + HH * KFC1;
    const int NP = 2 * LAYERS * G4H * HH;
    if (i < NA) { split1(fc0_w[i], f0h[i], f0l[i]); return; }
    if (i < NB) { int j = i - NA; split1(fc1_w[j], f1h[j], f1l[j]); return; }
    int i2 = i - NB;
    if (i2 < NP) {
        int sel = i2 >= NP / 2;
        int ii = sel ? i2 - NP / 2 : i2;
        int k = ii % HH;
        int j = (ii / HH) % G4H;
        int l = ii / (HH * G4H);
        int n = j >> 2, g = j & 3;
        const float* src = sel ? whh : wih;
        float v = src[(size_t)l * G4H * HH + (size_t)(g * HH + n) * HH + k];
        if (sel) split1(v, hhh[ii], hhl[ii]);
        else     split1(v, ihh[ii], ihl[ii]);
        return;
    }
    int i3 = i2 - NP;
    if (i3 < LAYERS * G4H) {
        int j = i3 % G4H;
        int l = i3 / G4H;
        int n = j >> 2, g = j & 3;
        bc[i3] = bih[l * G4H + g * HH + n] + bhh[l * G4H + g * HH + n];
        return;
    }
    int i4 = i3 - LAYERS * G4H;
    if (i4 < LAYERS * 8) ctr[i4] = 0;
}

// (B,W,H) fp32 -> (W*B, H) split bf16
__global__ void transpose_split(const float* __restrict__ src,
                                bf16* __restrict__ hi, bf16* __restrict__ lo)
{
    int i = blockIdx.x * blockDim.x + threadIdx.x;
    if (i >= TB * HH) return;
    int k = i % HH;
    int row = i / HH;
    int t = row / BB, b = row % BB;
    split1(src[((size_t)b * WW + t) * HH + k], hi[i], lo[i]);
}

// (W,B,H) split -> (B, W*H) split
__global__ void pack_split(const bf16* __restrict__ xhi, const bf16* __restrict__ xlo,
                           bf16* __restrict__ chi, bf16* __restrict__ clo)
{
    int i = blockIdx.x * blockDim.x + threadIdx.x;
    if (i >= BB * KFC1) return;
    int b = i / KFC1;
    int tk = i % KFC1;
    int t = tk / HH, k = tk % HH;
    size_t s = ((size_t)t * BB + b) * HH + k;
    chi[i] = xhi[s];
    clo[i] = xlo[s];
}

__global__ void reduce_fc1(const float* __restrict__ part, const float* __restrict__ b,
                           float* __restrict__ out)
{
    int i = blockIdx.x * blockDim.x + threadIdx.x;
    if (i >= BB * HH) return;
    float s = b[i % HH];
#pragma unroll
    for (int z = 0; z < SPLITK; z++) s += part[(size_t)z * BB * HH + i];
    out[i] = s;
}

// ---------------- host -------------------------------------------------------
extern "C" void kernel_launch(void* const* d_in, const int* in_sizes, int n_in,
                              void* d_out, int out_size)
{
    const float* xpos  = (const float*)d_in[0];
    const float* fc0_w = (const float*)d_in[1];
    const float* fc0_b = (const float*)d_in[2];
    const float* w_ih  = (const float*)d_in[3];
    const float* w_hh  = (const float*)d_in[4];
    const float* b_ih  = (const float*)d_in[5];
    const float* b_hh  = (const float*)d_in[6];
    const float* fc1_w = (const float*)d_in[7];
    const float* fc1_b = (const float*)d_in[8];
    float* out = (float*)d_out;

    bf16 *xAhi, *xAlo, *xBhi, *xBlo, *xcathi, *xcatlo;
    bf16 *fc0whi, *fc0wlo, *fc1whi, *fc1wlo, *wihhi, *wihlo, *whhhi, *whhlo;
    float *gx, *c, *bcomb, *part;
    int* ctr;
    cudaGetSymbolAddress((void**)&xAhi, g_xAhi);
    cudaGetSymbolAddress((void**)&xAlo, g_xAlo);
    cudaGetSymbolAddress((void**)&xBhi, g_xBhi);
    cudaGetSymbolAddress((void**)&xBlo, g_xBlo);
    cudaGetSymbolAddress((void**)&xcathi, g_xcathi);
    cudaGetSymbolAddress((void**)&xcatlo, g_xcatlo);
    cudaGetSymbolAddress((void**)&fc0whi, g_fc0whi);
    cudaGetSymbolAddress((void**)&fc0wlo, g_fc0wlo);
    cudaGetSymbolAddress((void**)&fc1whi, g_fc1whi);
    cudaGetSymbolAddress((void**)&fc1wlo, g_fc1wlo);
    cudaGetSymbolAddress((void**)&wihhi, g_wihhi);
    cudaGetSymbolAddress((void**)&wihlo, g_wihlo);
    cudaGetSymbolAddress((void**)&whhhi, g_whhhi);
    cudaGetSymbolAddress((void**)&whhlo, g_whhlo);
    cudaGetSymbolAddress((void**)&gx,    g_gx);
    cudaGetSymbolAddress((void**)&c,     g_c);
    cudaGetSymbolAddress((void**)&bcomb, g_bcomb);
    cudaGetSymbolAddress((void**)&part,  g_part);
    cudaGetSymbolAddress((void**)&ctr,   g_ctr);

    static bool once = false;
    if (!once) {
        cudaFuncSetAttribute(gemm_bf16<1>, cudaFuncAttributeMaxDynamicSharedMemorySize, SMEM_BYTES);
        cudaFuncSetAttribute(gemm_bf16<3>, cudaFuncAttributeMaxDynamicSharedMemorySize, SMEM_BYTES);
        cudaFuncSetAttribute(gemm_bf16<4>, cudaFuncAttributeMaxDynamicSharedMemorySize, SMEM_BYTES);
        cudaFuncSetAttribute(rec_layer,    cudaFuncAttributeMaxDynamicSharedMemorySize, RSMEM_BYTES);
        once = true;
    }

    const int EL = 256;

    // launch 0: input transpose/split
    transpose_split<<<(TB * HH + EL - 1) / EL, EL>>>(xpos, xcathi, xcatlo);

    // launch 1: merged prep (weights, biases, barrier-counter reset)
    {
        int n = HH * HH + HH * KFC1 + 2 * LAYERS * G4H * HH + LAYERS * G4H + LAYERS * 8;
        prep_all<<<(n + EL - 1) / EL, EL>>>(fc0_w, fc1_w, w_ih, w_hh, b_ih, b_hh,
                                            fc0whi, fc0wlo, fc1whi, fc1wlo,
                                            wihhi, wihlo, whhhi, whhlo, bcomb, ctr);
    }

    // launch 2: fc0 (split store)
    gemm_bf16<1><<<dim3(HH / 128, TB / 128, 1), 256, SMEM_BYTES>>>(
        xcathi, xcatlo, fc0whi, fc0wlo, fc0_b,
        nullptr, xAhi, xAlo, nullptr, TB, HH, HH, 1);

    for (int l = 0; l < LAYERS; l++) {
        bf16* ih = (l & 1) ? xBhi : xAhi;
        bf16* il = (l & 1) ? xBlo : xAlo;
        bf16* oh = (l & 1) ? xAhi : xBhi;
        bf16* ol = (l & 1) ? xAlo : xBlo;
        const bf16* wihh = wihhi + (size_t)l * G4H * HH;
        const bf16* wihl = wihlo + (size_t)l * G4H * HH;
        const bf16* whhh = whhhi + (size_t)l * G4H * HH;
        const bf16* whhl = whhlo + (size_t)l * G4H * HH;
        const float* bl_ = bcomb + (size_t)l * G4H;

        // input GEMM: t=0 rows -> fused cell into oh/ol; t>0 rows -> gx (+bias)
        gemm_bf16<3><<<dim3(G4H / 128, TB / 128, 1), 256, SMEM_BYTES>>>(
            ih, il, wihh, wihl, bl_,
            gx, oh, ol, c, TB, G4H, HH, 1);

        // persistent recurrent: steps 1..9 with internal grid barriers
        rec_layer<<<dim3(G4H / 64, BB / 128, 1), 256, RSMEM_BYTES>>>(
            oh, ol, whhh, whhl, gx, c, ctr + l * 8);
    }

    // final activations in xA (10 layers, even count)
    pack_split<<<(BB * KFC1 + EL - 1) / EL, EL>>>(xAhi, xAlo, xcathi, xcatlo);

    // fc1 split-K partials + reduce
    gemm_bf16<4><<<dim3(HH / 128, BB / 128, SPLITK), 256, SMEM_BYTES>>>(
        xcathi, xcatlo, fc1whi, fc1wlo, nullptr,
        part, nullptr, nullptr, nullptr, BB, HH, KFC1, SPLITK);
    reduce_fc1<<<(BB * HH + EL - 1) / EL, EL>>>(part, fc1_b, out);
}

// round 13
// speedup vs baseline: 1.0742x; 1.0307x over previous
#include <cuda_runtime.h>
#include <cuda_bf16.h>
#include <math.h>
#include <stdint.h>

#define HH 768
#define LAYERS 10
#define WW 10
#define BB 512
#define G4H 3072
#define TB 5120          // WW*BB
#define KFC1 (WW*HH)     // 7680
#define SPLITK 12

#define KT 32            // K-slab in elements
#define STRIDE 20        // u32 per smem row (16 used + 4 pad; ldmatrix conflict-free)
#define PLANE (128 * STRIDE)               // u32 per 128-row plane
#define SMEM_BYTES (2 * 4 * PLANE * 4)     // 81920 (128x128 GEMM, 2-stage)

#define BPLANE (64 * STRIDE)               // u32 per 64-row plane
#define RSTAGE_U32 (2 * PLANE + 2 * BPLANE)   // 7680 u32 = 30720 B
#define RSMEM_BYTES (3 * RSTAGE_U32 * 4)      // 92160 (layer kernel, 3-stage)

#define LGRID 296        // 148 SMs x occ 2 — all co-resident

typedef __nv_bfloat16 bf16;

// ---------------- scratch (device globals; allocation-free rule) -------------
__device__ bf16  g_xAhi[TB * HH], g_xAlo[TB * HH];
__device__ bf16  g_xBhi[TB * HH], g_xBlo[TB * HH];
__device__ float g_gx[TB * G4H];
__device__ float g_c[BB * HH];
__device__ bf16  g_xcathi[BB * KFC1], g_xcatlo[BB * KFC1];   // also fc0 input temp
__device__ bf16  g_fc0whi[HH * HH],   g_fc0wlo[HH * HH];
__device__ bf16  g_fc1whi[HH * KFC1], g_fc1wlo[HH * KFC1];
__device__ bf16  g_wihhi[LAYERS * G4H * HH], g_wihlo[LAYERS * G4H * HH];
__device__ bf16  g_whhhi[LAYERS * G4H * HH], g_whhlo[LAYERS * G4H * HH];
__device__ float g_bcomb[LAYERS * G4H];
__device__ float g_part[SPLITK * BB * HH];
__device__ int   g_ctr[LAYERS * 32];         // per layer: [0..9] work, [16..25] barrier

// ---------------- helpers ----------------------------------------------------
__device__ __forceinline__ void split1(float v, bf16& h, bf16& l)
{
    h = __float2bfloat16_rn(v);
    l = __float2bfloat16_rn(v - __bfloat162float(h));
}

__device__ __forceinline__ float sigm(float x) { return 1.0f / (1.0f + expf(-x)); }

__device__ __forceinline__ void cpasync16(void* dst, const void* src)
{
    uint32_t s = (uint32_t)__cvta_generic_to_shared(dst);
    asm volatile("cp.async.cg.shared.global [%0], [%1], 16;\n" :: "r"(s), "l"(src));
}
__device__ __forceinline__ void cp_commit() { asm volatile("cp.async.commit_group;\n"); }

__device__ __forceinline__ void mma_bf16(float* c, const uint32_t* a, const uint32_t* b)
{
    asm volatile(
        "mma.sync.aligned.m16n8k16.row.col.f32.bf16.bf16.f32 "
        "{%0,%1,%2,%3}, {%4,%5,%6,%7}, {%8,%9}, {%0,%1,%2,%3};"
        : "+f"(c[0]), "+f"(c[1]), "+f"(c[2]), "+f"(c[3])
        : "r"(a[0]), "r"(a[1]), "r"(a[2]), "r"(a[3]), "r"(b[0]), "r"(b[1]));
}

__device__ __forceinline__ void ldsm4(uint32_t* r, uint32_t saddr)
{
    asm volatile("ldmatrix.sync.aligned.m8n8.x4.shared.b16 {%0,%1,%2,%3}, [%4];"
                 : "=r"(r[0]), "=r"(r[1]), "=r"(r[2]), "=r"(r[3]) : "r"(saddr));
}

// ---------------- regular GEMM (128x128 tile, 2-stage, occ 2) ----------------
// MODE 1: (Chi,Clo) split bf16 = acc + bias     (fc0)
// MODE 4: raw fp32 partial store (split-K via blockIdx.z)  (fc1)
template <int MODE>
__global__ __launch_bounds__(256, 2) void gemm_bf16(
    const bf16* __restrict__ Ahi, const bf16* __restrict__ Alo,
    const bf16* __restrict__ Bhi, const bf16* __restrict__ Blo,
    const float* __restrict__ bias,
    float* __restrict__ Cf,
    bf16* __restrict__ Chi, bf16* __restrict__ Clo,
    int M, int N, int K, int nsplit)
{
    extern __shared__ uint32_t sm[];
    const int tid = threadIdx.x;
    const int lane = tid & 31;
    const int wid = tid >> 5;
    const int wm = wid >> 2;
    const int wn = wid & 3;
    const int bm = blockIdx.y * 128;
    const int bn = blockIdx.x * 128;
    const int q = lane >> 2;
    const int r = lane & 3;

    const int NS = K / KT;
    const int NSLABS = NS / nsplit;
    const int s0 = blockIdx.z * NSLABS;

    const int lrowA = ((lane >> 3) & 1) * 8 + (lane & 7);
    const int lchA  = (lane >> 4) & 1;
    const int lrowB = ((lane >> 4) & 1) * 8 + (lane & 7);
    const int lchB  = (lane >> 3) & 1;
    const uint32_t smem_b = (uint32_t)__cvta_generic_to_shared(sm);

    float acc[4][4][4];
#pragma unroll
    for (int i = 0; i < 4; i++)
#pragma unroll
        for (int j = 0; j < 4; j++)
#pragma unroll
            for (int v = 0; v < 4; v++) acc[i][j][v] = 0.f;

    auto issue = [&](int slab, int stage) {
        int k0 = slab * KT;
        uint32_t* base = sm + stage * 4 * PLANE;
#pragma unroll
        for (int i = 0; i < 2; i++) {
            int f = tid + i * 256;
            int m = f >> 2, cc = f & 3;
            size_t ga = (size_t)(bm + m) * K + k0 + cc * 8;
            size_t gb = (size_t)(bn + m) * K + k0 + cc * 8;
            int off = m * STRIDE + cc * 4;
            cpasync16(base + 0 * PLANE + off, Ahi + ga);
            cpasync16(base + 1 * PLANE + off, Alo + ga);
            cpasync16(base + 2 * PLANE + off, Bhi + gb);
            cpasync16(base + 3 * PLANE + off, Blo + gb);
        }
        cp_commit();
    };

    auto compute = [&](int stage) {
        uint32_t Ahb = smem_b + (stage * 4 + 0) * PLANE * 4;
        uint32_t Alb = smem_b + (stage * 4 + 1) * PLANE * 4;
        uint32_t Bhb = smem_b + (stage * 4 + 2) * PLANE * 4;
        uint32_t Blb = smem_b + (stage * 4 + 3) * PLANE * 4;
        uint32_t aoff = (uint32_t)((wm * 64 + lrowA) * STRIDE + lchA * 4) * 4;
        uint32_t boff = (uint32_t)((wn * 32 + lrowB) * STRIDE + lchB * 4) * 4;
#pragma unroll
        for (int k16 = 0; k16 < 2; k16++) {
            uint32_t kb = (uint32_t)(k16 * 8) * 4;
            uint32_t bh[4][2], bl[4][2];
#pragma unroll
            for (int p = 0; p < 2; p++) {
                uint32_t bo = boff + kb + (uint32_t)(p * 16 * STRIDE) * 4;
                uint32_t r4[4];
                ldsm4(r4, Bhb + bo);
                bh[p * 2][0] = r4[0]; bh[p * 2][1] = r4[1];
                bh[p * 2 + 1][0] = r4[2]; bh[p * 2 + 1][1] = r4[3];
                ldsm4(r4, Blb + bo);
                bl[p * 2][0] = r4[0]; bl[p * 2][1] = r4[1];
                bl[p * 2 + 1][0] = r4[2]; bl[p * 2 + 1][1] = r4[3];
            }
#pragma unroll
            for (int mi = 0; mi < 4; mi++) {
                uint32_t ao = aoff + kb + (uint32_t)(mi * 16 * STRIDE) * 4;
                uint32_t ah[4], al[4];
                ldsm4(ah, Ahb + ao);
#pragma unroll
                for (int ni = 0; ni < 4; ni++) {
                    mma_bf16(acc[mi][ni], ah, bh[ni]);
                    mma_bf16(acc[mi][ni], ah, bl[ni]);
                }
                ldsm4(al, Alb + ao);
#pragma unroll
                for (int ni = 0; ni < 4; ni++)
                    mma_bf16(acc[mi][ni], al, bh[ni]);
            }
        }
    };

    issue(s0, 0);
    if (NSLABS > 1) issue(s0 + 1, 1); else cp_commit();
    for (int s = 0; s < NSLABS; s++) {
        if (s + 1 < NSLABS) asm volatile("cp.async.wait_group 1;\n");
        else                asm volatile("cp.async.wait_group 0;\n");
        __syncthreads();
        compute(s & 1);
        __syncthreads();
        if (s + 2 < NSLABS) issue(s0 + s + 2, s & 1);
    }

#pragma unroll
    for (int mi = 0; mi < 4; mi++) {
#pragma unroll
        for (int ni = 0; ni < 4; ni++) {
            int m0 = bm + wm * 64 + mi * 16 + q;
            int n0 = bn + wn * 32 + ni * 8 + r * 2;
            float* a = acc[mi][ni];
            if (MODE == 1) {
                float bv0 = bias[n0], bv1 = bias[n0 + 1];
                float v00 = a[0] + bv0, v01 = a[1] + bv1;
                float v10 = a[2] + bv0, v11 = a[3] + bv1;
                bf16 h0, l0, h1, l1;
                split1(v00, h0, l0); split1(v01, h1, l1);
                *(__nv_bfloat162*)(Chi + (size_t)m0 * N + n0) = __nv_bfloat162(h0, h1);
                *(__nv_bfloat162*)(Clo + (size_t)m0 * N + n0) = __nv_bfloat162(l0, l1);
                split1(v10, h0, l0); split1(v11, h1, l1);
                *(__nv_bfloat162*)(Chi + (size_t)(m0 + 8) * N + n0) = __nv_bfloat162(h0, h1);
                *(__nv_bfloat162*)(Clo + (size_t)(m0 + 8) * N + n0) = __nv_bfloat162(l0, l1);
            } else {
                float* dst = Cf + ((size_t)blockIdx.z * M + m0) * N + n0;
                dst[0] = a[0]; dst[1] = a[1];
                dst += (size_t)8 * N;
                dst[0] = a[2]; dst[1] = a[3];
            }
        }
    }
}

// ---- fused persistent layer kernel: 296 CTAs, occ 2, work-stealing ----------
// Phase p=0:    384 tiles: [0,192) input t=0 with first-cell, [192,384) input t=1 -> gx
// Phase 1..8:   384 tiles: [0,192) rec step t=p (cell), [192,384) input t=p+1 -> gx
// Phase 9:      192 tiles: rec step t=9 (cell)
__global__ __launch_bounds__(256, 2) void layer_kernel(
    const bf16* __restrict__ ih, const bf16* __restrict__ il,
    bf16* __restrict__ oh, bf16* __restrict__ ol,
    const bf16* __restrict__ wihh, const bf16* __restrict__ wihl,
    const bf16* __restrict__ whhh, const bf16* __restrict__ whhl,
    const float* __restrict__ bias,
    float* __restrict__ gx, float* __restrict__ cstate,
    int* __restrict__ wctr, int* __restrict__ bctr)
{
    extern __shared__ uint32_t sm[];
    __shared__ int s_ticket;
    const int tid = threadIdx.x;
    const int lane = tid & 31;
    const int wid = tid >> 5;
    const int wm = wid >> 2;          // 0..1 (64 rows each)
    const int wn = wid & 3;           // 0..3 (16 cols each)
    const int q = lane >> 2;
    const int r = lane & 3;

    const int lrowA = ((lane >> 3) & 1) * 8 + (lane & 7);
    const int lchA  = (lane >> 4) & 1;
    const int lrowB = ((lane >> 4) & 1) * 8 + (lane & 7);
    const int lchB  = (lane >> 3) & 1;
    const uint32_t smem_b = (uint32_t)__cvta_generic_to_shared(sm);

    for (int p = 0; p < WW; p++) {
        const int ntile = (p == WW - 1) ? 192 : 384;

        for (;;) {
            if (tid == 0) s_ticket = atomicAdd(&wctr[p], 1);
            __syncthreads();
            int ticket = s_ticket;
            if (ticket >= ntile) break;

            // ---- decode tile ----
            int qq = (ticket < 192) ? ticket : ticket - 192;
            int bn = (qq % 48) * 64;
            int bm = (qq / 48) * 128;
            const bf16 *Ahi, *Alo, *Bhi, *Blo;
            int epi, tt;       // epi: 0 gx-store, 1 cell-first, 2 cell
            if (p == 0) {
                tt = (ticket < 192) ? 0 : 1;
                Ahi = ih + (size_t)tt * BB * HH; Alo = il + (size_t)tt * BB * HH;
                Bhi = wihh; Blo = wihl;
                epi = (ticket < 192) ? 1 : 0;
            } else if (ticket < 192) {
                tt = p;
                Ahi = oh + (size_t)(tt - 1) * BB * HH; Alo = ol + (size_t)(tt - 1) * BB * HH;
                Bhi = whhh; Blo = whhl;
                epi = 2;
            } else {
                tt = p + 1;
                Ahi = ih + (size_t)tt * BB * HH; Alo = il + (size_t)tt * BB * HH;
                Bhi = wihh; Blo = wihl;
                epi = 0;
            }

            // ---- 128x64 tile GEMM, K=768, 3-stage, 1 sync/slab ----
            float acc[4][2][4];
#pragma unroll
            for (int i = 0; i < 4; i++)
#pragma unroll
                for (int j = 0; j < 2; j++)
#pragma unroll
                    for (int v = 0; v < 4; v++) acc[i][j][v] = 0.f;

            auto issue = [&](int slab, int slot) {
                int k0 = slab * KT;
                uint32_t* base = sm + slot * RSTAGE_U32;
#pragma unroll
                for (int i = 0; i < 2; i++) {
                    int f = tid + i * 256;
                    int m = f >> 2, cc = f & 3;
                    size_t ga = (size_t)(bm + m) * HH + k0 + cc * 8;
                    int off = m * STRIDE + cc * 4;
                    cpasync16(base + off,         Ahi + ga);
                    cpasync16(base + PLANE + off, Alo + ga);
                }
                {
                    int m = tid >> 2, cc = tid & 3;
                    size_t gb = (size_t)(bn + m) * HH + k0 + cc * 8;
                    int off = m * STRIDE + cc * 4;
                    cpasync16(base + 2 * PLANE + off,          Bhi + gb);
                    cpasync16(base + 2 * PLANE + BPLANE + off, Blo + gb);
                }
                cp_commit();
            };

            auto compute = [&](int slot) {
                uint32_t Ahb = smem_b + (slot * RSTAGE_U32) * 4;
                uint32_t Alb = Ahb + PLANE * 4;
                uint32_t Bhb = Ahb + 2 * PLANE * 4;
                uint32_t Blb = Bhb + BPLANE * 4;
                uint32_t aoff = (uint32_t)((wm * 64 + lrowA) * STRIDE + lchA * 4) * 4;
                uint32_t boff = (uint32_t)((wn * 16 + lrowB) * STRIDE + lchB * 4) * 4;
#pragma unroll
                for (int k16 = 0; k16 < 2; k16++) {
                    uint32_t kb = (uint32_t)(k16 * 8) * 4;
                    uint32_t bh[2][2], bl[2][2];
                    {
                        uint32_t bo = boff + kb;
                        uint32_t r4[4];
                        ldsm4(r4, Bhb + bo);
                        bh[0][0] = r4[0]; bh[0][1] = r4[1];
                        bh[1][0] = r4[2]; bh[1][1] = r4[3];
                        ldsm4(r4, Blb + bo);
                        bl[0][0] = r4[0]; bl[0][1] = r4[1];
                        bl[1][0] = r4[2]; bl[1][1] = r4[3];
                    }
#pragma unroll
                    for (int mi = 0; mi < 4; mi++) {
                        uint32_t ao = aoff + kb + (uint32_t)(mi * 16 * STRIDE) * 4;
                        uint32_t ah[4], al[4];
                        ldsm4(ah, Ahb + ao);
#pragma unroll
                        for (int ni = 0; ni < 2; ni++) {
                            mma_bf16(acc[mi][ni], ah, bh[ni]);
                            mma_bf16(acc[mi][ni], ah, bl[ni]);
                        }
                        ldsm4(al, Alb + ao);
#pragma unroll
                        for (int ni = 0; ni < 2; ni++)
                            mma_bf16(acc[mi][ni], al, bh[ni]);
                    }
                }
            };

            issue(0, 0);
            issue(1, 1);
            for (int s = 0; s < 24; s++) {
                if (s < 23) asm volatile("cp.async.wait_group 1;\n");
                else        asm volatile("cp.async.wait_group 0;\n");
                __syncthreads();
                if (s + 2 < 24) issue(s + 2, (s + 2) % 3);
                compute(s % 3);
            }

            // ---- epilogue ----
            if (epi == 0) {
                float* gxt = gx + (size_t)tt * BB * G4H;
#pragma unroll
                for (int mi = 0; mi < 4; mi++) {
#pragma unroll
                    for (int ni = 0; ni < 2; ni++) {
                        int m0 = bm + wm * 64 + mi * 16 + q;
                        int n0 = bn + wn * 16 + ni * 8 + r * 2;
                        float* a = acc[mi][ni];
                        float bv0 = bias[n0], bv1 = bias[n0 + 1];
                        float* dst = gxt + (size_t)m0 * G4H + n0;
                        dst[0] = a[0] + bv0; dst[1] = a[1] + bv1;
                        dst += (size_t)8 * G4H;
                        dst[0] = a[2] + bv0; dst[1] = a[3] + bv1;
                    }
                }
            } else {
                const float* gxt = gx + (size_t)tt * BB * G4H;
                bf16* Chi = oh + (size_t)tt * BB * HH;
                bf16* Clo = ol + (size_t)tt * BB * HH;
#pragma unroll
                for (int mi = 0; mi < 4; mi++) {
#pragma unroll
                    for (int ni = 0; ni < 2; ni++) {
                        int m0 = bm + wm * 64 + mi * 16 + q;
                        int n0 = bn + wn * 16 + ni * 8 + r * 2;
                        float* a = acc[mi][ni];
                        float a0, a1, a2, a3;
                        if (epi == 1) {
                            float bv0 = bias[n0], bv1 = bias[n0 + 1];
                            a0 = a[0] + bv0; a1 = a[1] + bv1;
                            a2 = a[2] + bv0; a3 = a[3] + bv1;
                        } else {
                            float2 g0 = __ldcg((const float2*)(gxt + (size_t)m0 * G4H + n0));
                            float2 g1 = __ldcg((const float2*)(gxt + (size_t)(m0 + 8) * G4H + n0));
                            a0 = a[0] + g0.x; a1 = a[1] + g0.y;
                            a2 = a[2] + g1.x; a3 = a[3] + g1.y;
                        }
                        float p0 = __shfl_xor_sync(0xFFFFFFFFu, a0, 1);
                        float p1 = __shfl_xor_sync(0xFFFFFFFFu, a1, 1);
                        float p2 = __shfl_xor_sync(0xFFFFFFFFu, a2, 1);
                        float p3 = __shfl_xor_sync(0xFFFFFFFFu, a3, 1);
                        if ((r & 1) == 0) {
                            int n = n0 >> 2;
#pragma unroll
                            for (int rr = 0; rr < 2; rr++) {
                                int m = m0 + rr * 8;
                                float gi = rr ? a2 : a0;
                                float gf = rr ? a3 : a1;
                                float gg = rr ? p2 : p0;
                                float go = rr ? p3 : p1;
                                float cn;
                                if (epi == 1) {
                                    cn = sigm(gi) * tanhf(gg);
                                } else {
                                    float cold = __ldcg(cstate + (size_t)m * HH + n);
                                    cn = sigm(gf) * cold + sigm(gi) * tanhf(gg);
                                }
                                __stcg(cstate + (size_t)m * HH + n, cn);
                                float h = sigm(go) * tanhf(cn);
                                bf16 hh, hl;
                                split1(h, hh, hl);
                                Chi[(size_t)m * HH + n] = hh;
                                Clo[(size_t)m * HH + n] = hl;
                            }
                        }
                    }
                }
            }
        }

        // ---- phase barrier (all 296 CTAs) ----
        if (p < WW - 1) {
            __threadfence();
            __syncthreads();
            if (tid == 0) {
                atomicAdd(&bctr[p], 1);
                while (atomicAdd(&bctr[p], 0) < LGRID) __nanosleep(64);
            }
            __syncthreads();
        }
    }
}

// ---------------- prep (merged): weight splits + permute + bias + ctr reset --
__global__ void prep_all(const float* __restrict__ fc0_w, const float* __restrict__ fc1_w,
                         const float* __restrict__ wih, const float* __restrict__ whh,
                         const float* __restrict__ bih, const float* __restrict__ bhh,
                         bf16* __restrict__ f0h, bf16* __restrict__ f0l,
                         bf16* __restrict__ f1h, bf16* __restrict__ f1l,
                         bf16* __restrict__ ihh, bf16* __restrict__ ihl,
                         bf16* __restrict__ hhh, bf16* __restrict__ hhl,
                         float* __restrict__ bc, int* __restrict__ ctr)
{
    int i = blockIdx.x * blockDim.x + threadIdx.x;
    const int NA = HH * HH;
    const int NB = NA + HH * KFC1;
    const int NP = 2 * LAYERS * G4H * HH;
    if (i < NA) { split1(fc0_w[i], f0h[i], f0l[i]); return; }
    if (i < NB) { int j = i - NA; split1(fc1_w[j], f1h[j], f1l[j]); return; }
    int i2 = i - NB;
    if (i2 < NP) {
        int sel = i2 >= NP / 2;
        int ii = sel ? i2 - NP / 2 : i2;
        int k = ii % HH;
        int j = (ii / HH) % G4H;
        int l = ii / (HH * G4H);
        int n = j >> 2, g = j & 3;
        const float* src = sel ? whh : wih;
        float v = src[(size_t)l * G4H * HH + (size_t)(g * HH + n) * HH + k];
        if (sel) split1(v, hhh[ii], hhl[ii]);
        else     split1(v, ihh[ii], ihl[ii]);
        return;
    }
    int i3 = i2 - NP;
    if (i3 < LAYERS * G4H) {
        int j = i3 % G4H;
        int l = i3 / G4H;
        int n = j >> 2, g = j & 3;
        bc[i3] = bih[l * G4H + g * HH + n] + bhh[l * G4H + g * HH + n];
        return;
    }
    int i4 = i3 - LAYERS * G4H;
    if (i4 < LAYERS * 32) ctr[i4] = 0;
}

// (B,W,H) fp32 -> (W*B, H) split bf16
__global__ void transpose_split(const float* __restrict__ src,
                                bf16* __restrict__ hi, bf16* __restrict__ lo)
{
    int i = blockIdx.x * blockDim.x + threadIdx.x;
    if (i >= TB * HH) return;
    int k = i % HH;
    int row = i / HH;
    int t = row / BB, b = row % BB;
    split1(src[((size_t)b * WW + t) * HH + k], hi[i], lo[i]);
}

// (W,B,H) split -> (B, W*H) split
__global__ void pack_split(const bf16* __restrict__ xhi, const bf16* __restrict__ xlo,
                           bf16* __restrict__ chi, bf16* __restrict__ clo)
{
    int i = blockIdx.x * blockDim.x + threadIdx.x;
    if (i >= BB * KFC1) return;
    int b = i / KFC1;
    int tk = i % KFC1;
    int t = tk / HH, k = tk % HH;
    size_t s = ((size_t)t * BB + b) * HH + k;
    chi[i] = xhi[s];
    clo[i] = xlo[s];
}

__global__ void reduce_fc1(const float* __restrict__ part, const float* __restrict__ b,
                           float* __restrict__ out)
{
    int i = blockIdx.x * blockDim.x + threadIdx.x;
    if (i >= BB * HH) return;
    float s = b[i % HH];
#pragma unroll
    for (int z = 0; z < SPLITK; z++) s += part[(size_t)z * BB * HH + i];
    out[i] = s;
}

// ---------------- host -------------------------------------------------------
extern "C" void kernel_launch(void* const* d_in, const int* in_sizes, int n_in,
                              void* d_out, int out_size)
{
    const float* xpos  = (const float*)d_in[0];
    const float* fc0_w = (const float*)d_in[1];
    const float* fc0_b = (const float*)d_in[2];
    const float* w_ih  = (const float*)d_in[3];
    const float* w_hh  = (const float*)d_in[4];
    const float* b_ih  = (const float*)d_in[5];
    const float* b_hh  = (const float*)d_in[6];
    const float* fc1_w = (const float*)d_in[7];
    const float* fc1_b = (const float*)d_in[8];
    float* out = (float*)d_out;

    bf16 *xAhi, *xAlo, *xBhi, *xBlo, *xcathi, *xcatlo;
    bf16 *fc0whi, *fc0wlo, *fc1whi, *fc1wlo, *wihhi, *wihlo, *whhhi, *whhlo;
    float *gx, *c, *bcomb, *part;
    int* ctr;
    cudaGetSymbolAddress((void**)&xAhi, g_xAhi);
    cudaGetSymbolAddress((void**)&xAlo, g_xAlo);
    cudaGetSymbolAddress((void**)&xBhi, g_xBhi);
    cudaGetSymbolAddress((void**)&xBlo, g_xBlo);
    cudaGetSymbolAddress((void**)&xcathi, g_xcathi);
    cudaGetSymbolAddress((void**)&xcatlo, g_xcatlo);
    cudaGetSymbolAddress((void**)&fc0whi, g_fc0whi);
    cudaGetSymbolAddress((void**)&fc0wlo, g_fc0wlo);
    cudaGetSymbolAddress((void**)&fc1whi, g_fc1whi);
    cudaGetSymbolAddress((void**)&fc1wlo, g_fc1wlo);
    cudaGetSymbolAddress((void**)&wihhi, g_wihhi);
    cudaGetSymbolAddress((void**)&wihlo, g_wihlo);
    cudaGetSymbolAddress((void**)&whhhi, g_whhhi);
    cudaGetSymbolAddress((void**)&whhlo, g_whhlo);
    cudaGetSymbolAddress((void**)&gx,    g_gx);
    cudaGetSymbolAddress((void**)&c,     g_c);
    cudaGetSymbolAddress((void**)&bcomb, g_bcomb);
    cudaGetSymbolAddress((void**)&part,  g_part);
    cudaGetSymbolAddress((void**)&ctr,   g_ctr);

    static bool once = false;
    if (!once) {
        cudaFuncSetAttribute(gemm_bf16<1>, cudaFuncAttributeMaxDynamicSharedMemorySize, SMEM_BYTES);
        cudaFuncSetAttribute(gemm_bf16<4>, cudaFuncAttributeMaxDynamicSharedMemorySize, SMEM_BYTES);
        cudaFuncSetAttribute(layer_kernel, cudaFuncAttributeMaxDynamicSharedMemorySize, RSMEM_BYTES);
        once = true;
    }

    const int EL = 256;

    // launch 0: input transpose/split
    transpose_split<<<(TB * HH + EL - 1) / EL, EL>>>(xpos, xcathi, xcatlo);

    // launch 1: merged prep (weights, biases, counter reset)
    {
        int n = HH * HH + HH * KFC1 + 2 * LAYERS * G4H * HH + LAYERS * G4H + LAYERS * 32;
        prep_all<<<(n + EL - 1) / EL, EL>>>(fc0_w, fc1_w, w_ih, w_hh, b_ih, b_hh,
                                            fc0whi, fc0wlo, fc1whi, fc1wlo,
                                            wihhi, wihlo, whhhi, whhlo, bcomb, ctr);
    }

    // launch 2: fc0 (split store)
    gemm_bf16<1><<<dim3(HH / 128, TB / 128, 1), 256, SMEM_BYTES>>>(
        xcathi, xcatlo, fc0whi, fc0wlo, fc0_b,
        nullptr, xAhi, xAlo, TB, HH, HH, 1);

    for (int l = 0; l < LAYERS; l++) {
        bf16* ih = (l & 1) ? xBhi : xAhi;
        bf16* il = (l & 1) ? xBlo : xAlo;
        bf16* oh = (l & 1) ? xAhi : xBhi;
        bf16* ol = (l & 1) ? xAlo : xBlo;

        layer_kernel<<<LGRID, 256, RSMEM_BYTES>>>(
            ih, il, oh, ol,
            wihhi + (size_t)l * G4H * HH, wihlo + (size_t)l * G4H * HH,
            whhhi + (size_t)l * G4H * HH, whhlo + (size_t)l * G4H * HH,
            bcomb + (size_t)l * G4H, gx, c,
            ctr + l * 32, ctr + l * 32 + 16);
    }

    // final activations in xA (10 layers, even count)
    pack_split<<<(BB * KFC1 + EL - 1) / EL, EL>>>(xAhi, xAlo, xcathi, xcatlo);

    // fc1 split-K partials + reduce
    gemm_bf16<4><<<dim3(HH / 128, BB / 128, SPLITK), 256, SMEM_BYTES>>>(
        xcathi, xcatlo, fc1whi, fc1wlo, nullptr,
        part, nullptr, nullptr, BB, HH, KFC1, SPLITK);
    reduce_fc1<<<(BB * HH + EL - 1) / EL, EL>>>(part, fc1_b, out);
}

// round 14
// speedup vs baseline: 1.4300x; 1.3312x over previous
#include <cuda_runtime.h>
#include <cuda_bf16.h>
#include <math.h>
#include <stdint.h>

#define HH 768
#define LAYERS 10
#define WW 10
#define BB 512
#define G4H 3072
#define TB 5120          // WW*BB
#define KFC1 (WW*HH)     // 7680
#define SPLITK 12

#define KT 32            // K-slab in elements
#define STRIDE 20        // u32 per smem row (16 used + 4 pad; ldmatrix conflict-free)
#define PLANE (128 * STRIDE)               // u32 per 128-row plane
#define SMEM_BYTES (2 * 4 * PLANE * 4)     // 81920 (128x128 GEMM, 2-stage)

#define BPLANE (64 * STRIDE)               // u32 per 64-row plane
#define RSTAGE_U32 (2 * PLANE + 2 * BPLANE)   // 7680 u32 = 30720 B
#define RSMEM_BYTES (3 * RSTAGE_U32 * 4)      // 92160 (mega kernel, 3-stage)

#define LGRID 296        // 148 SMs x occ 2 — all co-resident
#define NBATCH 400       // LAYERS * WW * 4 chains
#define NTICK  19200     // NBATCH * 48

typedef __nv_bfloat16 bf16;

// ---------------- scratch (device globals; allocation-free rule) -------------
__device__ bf16  g_xhi[11 * TB * HH], g_xlo[11 * TB * HH];   // x[l][t][b][h], l=0..10
__device__ float g_c[LAYERS * BB * HH];                      // per-layer cell state
__device__ bf16  g_xcathi[BB * KFC1], g_xcatlo[BB * KFC1];   // fc0 input / fc1 packed
__device__ bf16  g_fc0whi[HH * HH],   g_fc0wlo[HH * HH];
__device__ bf16  g_fc1whi[HH * KFC1], g_fc1wlo[HH * KFC1];
__device__ bf16  g_wihhi[LAYERS * G4H * HH], g_wihlo[LAYERS * G4H * HH];
__device__ bf16  g_whhhi[LAYERS * G4H * HH], g_whhlo[LAYERS * G4H * HH];
__device__ float g_bcomb[LAYERS * G4H];
__device__ float g_part[SPLITK * BB * HH];
// sched: [0..399] done, [400..799] dep, [800..1199] readyq, [1200] qhead, [1201] qtail
__device__ int   g_sched[1280];

// ---------------- helpers ----------------------------------------------------
__device__ __forceinline__ void split1(float v, bf16& h, bf16& l)
{
    h = __float2bfloat16_rn(v);
    l = __float2bfloat16_rn(v - __bfloat162float(h));
}

__device__ __forceinline__ float sigm(float x) { return 1.0f / (1.0f + expf(-x)); }

__device__ __forceinline__ void cpasync16(void* dst, const void* src)
{
    uint32_t s = (uint32_t)__cvta_generic_to_shared(dst);
    asm volatile("cp.async.cg.shared.global [%0], [%1], 16;\n" :: "r"(s), "l"(src));
}
__device__ __forceinline__ void cp_commit() { asm volatile("cp.async.commit_group;\n"); }

__device__ __forceinline__ void mma_bf16(float* c, const uint32_t* a, const uint32_t* b)
{
    asm volatile(
        "mma.sync.aligned.m16n8k16.row.col.f32.bf16.bf16.f32 "
        "{%0,%1,%2,%3}, {%4,%5,%6,%7}, {%8,%9}, {%0,%1,%2,%3};"
        : "+f"(c[0]), "+f"(c[1]), "+f"(c[2]), "+f"(c[3])
        : "r"(a[0]), "r"(a[1]), "r"(a[2]), "r"(a[3]), "r"(b[0]), "r"(b[1]));
}

__device__ __forceinline__ void ldsm4(uint32_t* r, uint32_t saddr)
{
    asm volatile("ldmatrix.sync.aligned.m8n8.x4.shared.b16 {%0,%1,%2,%3}, [%4];"
                 : "=r"(r[0]), "=r"(r[1]), "=r"(r[2]), "=r"(r[3]) : "r"(saddr));
}

// ---------------- regular GEMM (128x128 tile, 2-stage, occ 2) ----------------
// MODE 1: (Chi,Clo) split bf16 = acc + bias     (fc0)
// MODE 4: raw fp32 partial store (split-K via blockIdx.z)  (fc1)
template <int MODE>
__global__ __launch_bounds__(256, 2) void gemm_bf16(
    const bf16* __restrict__ Ahi, const bf16* __restrict__ Alo,
    const bf16* __restrict__ Bhi, const bf16* __restrict__ Blo,
    const float* __restrict__ bias,
    float* __restrict__ Cf,
    bf16* __restrict__ Chi, bf16* __restrict__ Clo,
    int M, int N, int K, int nsplit)
{
    extern __shared__ uint32_t sm[];
    const int tid = threadIdx.x;
    const int lane = tid & 31;
    const int wid = tid >> 5;
    const int wm = wid >> 2;
    const int wn = wid & 3;
    const int bm = blockIdx.y * 128;
    const int bn = blockIdx.x * 128;
    const int q = lane >> 2;
    const int r = lane & 3;

    const int NS = K / KT;
    const int NSLABS = NS / nsplit;
    const int s0 = blockIdx.z * NSLABS;

    const int lrowA = ((lane >> 3) & 1) * 8 + (lane & 7);
    const int lchA  = (lane >> 4) & 1;
    const int lrowB = ((lane >> 4) & 1) * 8 + (lane & 7);
    const int lchB  = (lane >> 3) & 1;
    const uint32_t smem_b = (uint32_t)__cvta_generic_to_shared(sm);

    float acc[4][4][4];
#pragma unroll
    for (int i = 0; i < 4; i++)
#pragma unroll
        for (int j = 0; j < 4; j++)
#pragma unroll
            for (int v = 0; v < 4; v++) acc[i][j][v] = 0.f;

    auto issue = [&](int slab, int stage) {
        int k0 = slab * KT;
        uint32_t* base = sm + stage * 4 * PLANE;
#pragma unroll
        for (int i = 0; i < 2; i++) {
            int f = tid + i * 256;
            int m = f >> 2, cc = f & 3;
            size_t ga = (size_t)(bm + m) * K + k0 + cc * 8;
            size_t gb = (size_t)(bn + m) * K + k0 + cc * 8;
            int off = m * STRIDE + cc * 4;
            cpasync16(base + 0 * PLANE + off, Ahi + ga);
            cpasync16(base + 1 * PLANE + off, Alo + ga);
            cpasync16(base + 2 * PLANE + off, Bhi + gb);
            cpasync16(base + 3 * PLANE + off, Blo + gb);
        }
        cp_commit();
    };

    auto compute = [&](int stage) {
        uint32_t Ahb = smem_b + (stage * 4 + 0) * PLANE * 4;
        uint32_t Alb = smem_b + (stage * 4 + 1) * PLANE * 4;
        uint32_t Bhb = smem_b + (stage * 4 + 2) * PLANE * 4;
        uint32_t Blb = smem_b + (stage * 4 + 3) * PLANE * 4;
        uint32_t aoff = (uint32_t)((wm * 64 + lrowA) * STRIDE + lchA * 4) * 4;
        uint32_t boff = (uint32_t)((wn * 32 + lrowB) * STRIDE + lchB * 4) * 4;
#pragma unroll
        for (int k16 = 0; k16 < 2; k16++) {
            uint32_t kb = (uint32_t)(k16 * 8) * 4;
            uint32_t bh[4][2], bl[4][2];
#pragma unroll
            for (int p = 0; p < 2; p++) {
                uint32_t bo = boff + kb + (uint32_t)(p * 16 * STRIDE) * 4;
                uint32_t r4[4];
                ldsm4(r4, Bhb + bo);
                bh[p * 2][0] = r4[0]; bh[p * 2][1] = r4[1];
                bh[p * 2 + 1][0] = r4[2]; bh[p * 2 + 1][1] = r4[3];
                ldsm4(r4, Blb + bo);
                bl[p * 2][0] = r4[0]; bl[p * 2][1] = r4[1];
                bl[p * 2 + 1][0] = r4[2]; bl[p * 2 + 1][1] = r4[3];
            }
#pragma unroll
            for (int mi = 0; mi < 4; mi++) {
                uint32_t ao = aoff + kb + (uint32_t)(mi * 16 * STRIDE) * 4;
                uint32_t ah[4], al[4];
                ldsm4(ah, Ahb + ao);
#pragma unroll
                for (int ni = 0; ni < 4; ni++) {
                    mma_bf16(acc[mi][ni], ah, bh[ni]);
                    mma_bf16(acc[mi][ni], ah, bl[ni]);
                }
                ldsm4(al, Alb + ao);
#pragma unroll
                for (int ni = 0; ni < 4; ni++)
                    mma_bf16(acc[mi][ni], al, bh[ni]);
            }
        }
    };

    issue(s0, 0);
    if (NSLABS > 1) issue(s0 + 1, 1); else cp_commit();
    for (int s = 0; s < NSLABS; s++) {
        if (s + 1 < NSLABS) asm volatile("cp.async.wait_group 1;\n");
        else                asm volatile("cp.async.wait_group 0;\n");
        __syncthreads();
        compute(s & 1);
        __syncthreads();
        if (s + 2 < NSLABS) issue(s0 + s + 2, s & 1);
    }

#pragma unroll
    for (int mi = 0; mi < 4; mi++) {
#pragma unroll
        for (int ni = 0; ni < 4; ni++) {
            int m0 = bm + wm * 64 + mi * 16 + q;
            int n0 = bn + wn * 32 + ni * 8 + r * 2;
            float* a = acc[mi][ni];
            if (MODE == 1) {
                float bv0 = bias[n0], bv1 = bias[n0 + 1];
                float v00 = a[0] + bv0, v01 = a[1] + bv1;
                float v10 = a[2] + bv0, v11 = a[3] + bv1;
                bf16 h0, l0, h1, l1;
                split1(v00, h0, l0); split1(v01, h1, l1);
                *(__nv_bfloat162*)(Chi + (size_t)m0 * N + n0) = __nv_bfloat162(h0, h1);
                *(__nv_bfloat162*)(Clo + (size_t)m0 * N + n0) = __nv_bfloat162(l0, l1);
                split1(v10, h0, l0); split1(v11, h1, l1);
                *(__nv_bfloat162*)(Chi + (size_t)(m0 + 8) * N + n0) = __nv_bfloat162(h0, h1);
                *(__nv_bfloat162*)(Clo + (size_t)(m0 + 8) * N + n0) = __nv_bfloat162(l0, l1);
            } else {
                float* dst = Cf + ((size_t)blockIdx.z * M + m0) * N + n0;
                dst[0] = a[0]; dst[1] = a[1];
                dst += (size_t)8 * N;
                dst[0] = a[2]; dst[1] = a[3];
            }
        }
    }
}

// ---- dataflow-scheduled mega kernel: all 10 layers x 10 steps ---------------
// batch id = l*40 + t*4 + chain; 48 tiles (bn) per batch; tile = fused
// (x[l][t]·wih^T + h[t-1]·whh^T) K=1536 GEMM + LSTM cell -> x[l+1][t].
__global__ __launch_bounds__(256, 2) void mega_kernel(
    bf16* __restrict__ xhi, bf16* __restrict__ xlo,
    const bf16* __restrict__ wihhi, const bf16* __restrict__ wihlo,
    const bf16* __restrict__ whhhi, const bf16* __restrict__ whhlo,
    const float* __restrict__ bcomb, float* __restrict__ call,
    int* __restrict__ sched)
{
    extern __shared__ uint32_t sm[];
    __shared__ int s_ticket, s_batch;
    const int tid = threadIdx.x;
    const int lane = tid & 31;
    const int wid = tid >> 5;
    const int wm = wid >> 2;          // 0..1 (64 rows each)
    const int wn = wid & 3;           // 0..3 (16 cols each)
    const int q = lane >> 2;
    const int r = lane & 3;

    const int lrowA = ((lane >> 3) & 1) * 8 + (lane & 7);
    const int lchA  = (lane >> 4) & 1;
    const int lrowB = ((lane >> 4) & 1) * 8 + (lane & 7);
    const int lchB  = (lane >> 3) & 1;
    const uint32_t smem_b = (uint32_t)__cvta_generic_to_shared(sm);

    int* done  = sched;
    int* dep   = sched + 400;
    int* rq    = sched + 800;

    for (;;) {
        if (tid == 0) s_ticket = atomicAdd(&sched[1200], 1);
        __syncthreads();
        int ticket = s_ticket;
        if (ticket >= NTICK) break;
        int slot = ticket / 48;
        int bn = (ticket % 48) * 64;
        if (tid == 0) {
            int b;
            while ((b = __ldcg(&rq[slot])) < 0) __nanosleep(100);
            s_batch = b;
        }
        __syncthreads();
        int batch = s_batch;
        int ch = batch & 3;
        int t  = (batch >> 2) % 10;
        int l  = batch / 40;
        int bm = ch * 128;

        const bf16* A1h = xhi + ((size_t)l * WW + t) * BB * HH;
        const bf16* A1l = xlo + ((size_t)l * WW + t) * BB * HH;
        const bf16* A2h = xhi + ((size_t)(l + 1) * WW + (t - 1)) * BB * HH;
        const bf16* A2l = xlo + ((size_t)(l + 1) * WW + (t - 1)) * BB * HH;
        const bf16* B1h = wihhi + (size_t)l * G4H * HH;
        const bf16* B1l = wihlo + (size_t)l * G4H * HH;
        const bf16* B2h = whhhi + (size_t)l * G4H * HH;
        const bf16* B2l = whhlo + (size_t)l * G4H * HH;
        const int NSLAB = t ? 48 : 24;

        float acc[4][2][4];
#pragma unroll
        for (int i = 0; i < 4; i++)
#pragma unroll
            for (int j = 0; j < 2; j++)
#pragma unroll
                for (int v = 0; v < 4; v++) acc[i][j][v] = 0.f;

        auto issue = [&](int slab, int slot3) {
            int seg2 = slab >= 24;
            int k0 = (seg2 ? slab - 24 : slab) * KT;
            const bf16* Ah = seg2 ? A2h : A1h;
            const bf16* Al = seg2 ? A2l : A1l;
            const bf16* Bh = seg2 ? B2h : B1h;
            const bf16* Bl = seg2 ? B2l : B1l;
            uint32_t* base = sm + slot3 * RSTAGE_U32;
#pragma unroll
            for (int i = 0; i < 2; i++) {
                int f = tid + i * 256;
                int m = f >> 2, cc = f & 3;
                size_t ga = (size_t)(bm + m) * HH + k0 + cc * 8;
                int off = m * STRIDE + cc * 4;
                cpasync16(base + off,         Ah + ga);
                cpasync16(base + PLANE + off, Al + ga);
            }
            {
                int m = tid >> 2, cc = tid & 3;
                size_t gb = (size_t)(bn + m) * HH + k0 + cc * 8;
                int off = m * STRIDE + cc * 4;
                cpasync16(base + 2 * PLANE + off,          Bh + gb);
                cpasync16(base + 2 * PLANE + BPLANE + off, Bl + gb);
            }
            cp_commit();
        };

        auto compute = [&](int slot3) {
            uint32_t Ahb = smem_b + (slot3 * RSTAGE_U32) * 4;
            uint32_t Alb = Ahb + PLANE * 4;
            uint32_t Bhb = Ahb + 2 * PLANE * 4;
            uint32_t Blb = Bhb + BPLANE * 4;
            uint32_t aoff = (uint32_t)((wm * 64 + lrowA) * STRIDE + lchA * 4) * 4;
            uint32_t boff = (uint32_t)((wn * 16 + lrowB) * STRIDE + lchB * 4) * 4;
#pragma unroll
            for (int k16 = 0; k16 < 2; k16++) {
                uint32_t kb = (uint32_t)(k16 * 8) * 4;
                uint32_t bh[2][2], bl[2][2];
                {
                    uint32_t bo = boff + kb;
                    uint32_t r4[4];
                    ldsm4(r4, Bhb + bo);
                    bh[0][0] = r4[0]; bh[0][1] = r4[1];
                    bh[1][0] = r4[2]; bh[1][1] = r4[3];
                    ldsm4(r4, Blb + bo);
                    bl[0][0] = r4[0]; bl[0][1] = r4[1];
                    bl[1][0] = r4[2]; bl[1][1] = r4[3];
                }
#pragma unroll
                for (int mi = 0; mi < 4; mi++) {
                    uint32_t ao = aoff + kb + (uint32_t)(mi * 16 * STRIDE) * 4;
                    uint32_t ah[4], al[4];
                    ldsm4(ah, Ahb + ao);
#pragma unroll
                    for (int ni = 0; ni < 2; ni++) {
                        mma_bf16(acc[mi][ni], ah, bh[ni]);
                        mma_bf16(acc[mi][ni], ah, bl[ni]);
                    }
                    ldsm4(al, Alb + ao);
#pragma unroll
                    for (int ni = 0; ni < 2; ni++)
                        mma_bf16(acc[mi][ni], al, bh[ni]);
                }
            }
        };

        issue(0, 0);
        issue(1, 1);
        for (int s = 0; s < NSLAB; s++) {
            if (s < NSLAB - 1) asm volatile("cp.async.wait_group 1;\n");
            else               asm volatile("cp.async.wait_group 0;\n");
            __syncthreads();
            if (s + 2 < NSLAB) issue(s + 2, (s + 2) % 3);
            compute(s % 3);
        }

        // ---- LSTM cell epilogue -> x[l+1][t] ----
        {
            const float* bias = bcomb + (size_t)l * G4H;
            float* cst = call + (size_t)l * BB * HH;
            bf16* Chi = xhi + ((size_t)(l + 1) * WW + t) * BB * HH;
            bf16* Clo = xlo + ((size_t)(l + 1) * WW + t) * BB * HH;
#pragma unroll
            for (int mi = 0; mi < 4; mi++) {
#pragma unroll
                for (int ni = 0; ni < 2; ni++) {
                    int m0 = bm + wm * 64 + mi * 16 + q;
                    int n0 = bn + wn * 16 + ni * 8 + r * 2;
                    float* a = acc[mi][ni];
                    float bv0 = bias[n0], bv1 = bias[n0 + 1];
                    float a0 = a[0] + bv0, a1 = a[1] + bv1;
                    float a2 = a[2] + bv0, a3 = a[3] + bv1;
                    float p0 = __shfl_xor_sync(0xFFFFFFFFu, a0, 1);
                    float p1 = __shfl_xor_sync(0xFFFFFFFFu, a1, 1);
                    float p2 = __shfl_xor_sync(0xFFFFFFFFu, a2, 1);
                    float p3 = __shfl_xor_sync(0xFFFFFFFFu, a3, 1);
                    if ((r & 1) == 0) {
                        int n = n0 >> 2;
#pragma unroll
                        for (int rr = 0; rr < 2; rr++) {
                            int m = m0 + rr * 8;
                            float gi = rr ? a2 : a0;
                            float gf = rr ? a3 : a1;
                            float gg = rr ? p2 : p0;
                            float go = rr ? p3 : p1;
                            float cn;
                            if (t == 0) {
                                cn = sigm(gi) * tanhf(gg);
                            } else {
                                float cold = __ldcg(cst + (size_t)m * HH + n);
                                cn = sigm(gf) * cold + sigm(gi) * tanhf(gg);
                            }
                            __stcg(cst + (size_t)m * HH + n, cn);
                            float h = sigm(go) * tanhf(cn);
                            bf16 hh, hl;
                            split1(h, hh, hl);
                            Chi[(size_t)m * HH + n] = hh;
                            Clo[(size_t)m * HH + n] = hl;
                        }
                    }
                }
            }
        }

        // ---- publish completion ----
        __threadfence();
        __syncthreads();
        if (tid == 0) {
            if (atomicAdd(&done[batch], 1) == 47) {
                if (l < LAYERS - 1) {
                    if (atomicSub(&dep[batch + 40], 1) == 1) {
                        int p = atomicAdd(&sched[1201], 1);
                        __stcg(&rq[p], batch + 40);
                    }
                }
                if (t < WW - 1) {
                    if (atomicSub(&dep[batch + 4], 1) == 1) {
                        int p = atomicAdd(&sched[1201], 1);
                        __stcg(&rq[p], batch + 4);
                    }
                }
            }
        }
    }
}

// ---------------- prep (merged): weight splits + bias + scheduler init -------
__global__ void prep_all(const float* __restrict__ fc0_w, const float* __restrict__ fc1_w,
                         const float* __restrict__ wih, const float* __restrict__ whh,
                         const float* __restrict__ bih, const float* __restrict__ bhh,
                         bf16* __restrict__ f0h, bf16* __restrict__ f0l,
                         bf16* __restrict__ f1h, bf16* __restrict__ f1l,
                         bf16* __restrict__ ihh, bf16* __restrict__ ihl,
                         bf16* __restrict__ hhh, bf16* __restrict__ hhl,
                         float* __restrict__ bc, int* __restrict__ sched)
{
    int i = blockIdx.x * blockDim.x + threadIdx.x;
    const int NA = HH * HH;
    const int NB = NA + HH * KFC1;
    const int NP = 2 * LAYERS * G4H * HH;
    if (i < NA) { split1(fc0_w[i], f0h[i], f0l[i]); return; }
    if (i < NB) { int j = i - NA; split1(fc1_w[j], f1h[j], f1l[j]); return; }
    int i2 = i - NB;
    if (i2 < NP) {
        int sel = i2 >= NP / 2;
        int ii = sel ? i2 - NP / 2 : i2;
        int k = ii % HH;
        int j = (ii / HH) % G4H;
        int l = ii / (HH * G4H);
        int n = j >> 2, g = j & 3;
        const float* src = sel ? whh : wih;
        float v = src[(size_t)l * G4H * HH + (size_t)(g * HH + n) * HH + k];
        if (sel) split1(v, hhh[ii], hhl[ii]);
        else     split1(v, ihh[ii], ihl[ii]);
        return;
    }
    int i3 = i2 - NP;
    if (i3 < LAYERS * G4H) {
        int j = i3 % G4H;
        int l = i3 / G4H;
        int n = j >> 2, g = j & 3;
        bc[i3] = bih[l * G4H + g * HH + n] + bhh[l * G4H + g * HH + n];
        return;
    }
    int i4 = i3 - LAYERS * G4H;
    if (i4 < 1280) {
        if (i4 < 400) sched[i4] = 0;                       // done
        else if (i4 < 800) {                               // dep
            int b = i4 - 400;
            int l = b / 40, tt = (b % 40) >> 2;
            sched[i4] = (l > 0 ? 1 : 0) + (tt > 0 ? 1 : 0);
        } else if (i4 < 1200) {                            // readyq
            int s = i4 - 800;
            sched[i4] = (s < 4) ? s : -1;                  // batches (l=0,t=0,c=0..3)
        } else if (i4 == 1200) sched[i4] = 0;              // qhead
        else sched[i4] = 4;                                // qtail
    }
}

// (B,W,H) fp32 -> (W*B, H) split bf16
__global__ void transpose_split(const float* __restrict__ src,
                                bf16* __restrict__ hi, bf16* __restrict__ lo)
{
    int i = blockIdx.x * blockDim.x + threadIdx.x;
    if (i >= TB * HH) return;
    int k = i % HH;
    int row = i / HH;
    int t = row / BB, b = row % BB;
    split1(src[((size_t)b * WW + t) * HH + k], hi[i], lo[i]);
}

// (W,B,H) split -> (B, W*H) split
__global__ void pack_split(const bf16* __restrict__ xhi, const bf16* __restrict__ xlo,
                           bf16* __restrict__ chi, bf16* __restrict__ clo)
{
    int i = blockIdx.x * blockDim.x + threadIdx.x;
    if (i >= BB * KFC1) return;
    int b = i / KFC1;
    int tk = i % KFC1;
    int t = tk / HH, k = tk % HH;
    size_t s = ((size_t)t * BB + b) * HH + k;
    chi[i] = xhi[s];
    clo[i] = xlo[s];
}

__global__ void reduce_fc1(const float* __restrict__ part, const float* __restrict__ b,
                           float* __restrict__ out)
{
    int i = blockIdx.x * blockDim.x + threadIdx.x;
    if (i >= BB * HH) return;
    float s = b[i % HH];
#pragma unroll
    for (int z = 0; z < SPLITK; z++) s += part[(size_t)z * BB * HH + i];
    out[i] = s;
}

// ---------------- host -------------------------------------------------------
extern "C" void kernel_launch(void* const* d_in, const int* in_sizes, int n_in,
                              void* d_out, int out_size)
{
    const float* xpos  = (const float*)d_in[0];
    const float* fc0_w = (const float*)d_in[1];
    const float* fc0_b = (const float*)d_in[2];
    const float* w_ih  = (const float*)d_in[3];
    const float* w_hh  = (const float*)d_in[4];
    const float* b_ih  = (const float*)d_in[5];
    const float* b_hh  = (const float*)d_in[6];
    const float* fc1_w = (const float*)d_in[7];
    const float* fc1_b = (const float*)d_in[8];
    float* out = (float*)d_out;

    bf16 *xhi, *xlo, *xcathi, *xcatlo;
    bf16 *fc0whi, *fc0wlo, *fc1whi, *fc1wlo, *wihhi, *wihlo, *whhhi, *whhlo;
    float *c, *bcomb, *part;
    int* sched;
    cudaGetSymbolAddress((void**)&xhi,   g_xhi);
    cudaGetSymbolAddress((void**)&xlo,   g_xlo);
    cudaGetSymbolAddress((void**)&xcathi, g_xcathi);
    cudaGetSymbolAddress((void**)&xcatlo, g_xcatlo);
    cudaGetSymbolAddress((void**)&fc0whi, g_fc0whi);
    cudaGetSymbolAddress((void**)&fc0wlo, g_fc0wlo);
    cudaGetSymbolAddress((void**)&fc1whi, g_fc1whi);
    cudaGetSymbolAddress((void**)&fc1wlo, g_fc1wlo);
    cudaGetSymbolAddress((void**)&wihhi, g_wihhi);
    cudaGetSymbolAddress((void**)&wihlo, g_wihlo);
    cudaGetSymbolAddress((void**)&whhhi, g_whhhi);
    cudaGetSymbolAddress((void**)&whhlo, g_whhlo);
    cudaGetSymbolAddress((void**)&c,     g_c);
    cudaGetSymbolAddress((void**)&bcomb, g_bcomb);
    cudaGetSymbolAddress((void**)&part,  g_part);
    cudaGetSymbolAddress((void**)&sched, g_sched);

    static bool once = false;
    if (!once) {
        cudaFuncSetAttribute(gemm_bf16<1>, cudaFuncAttributeMaxDynamicSharedMemorySize, SMEM_BYTES);
        cudaFuncSetAttribute(gemm_bf16<4>, cudaFuncAttributeMaxDynamicSharedMemorySize, SMEM_BYTES);
        cudaFuncSetAttribute(mega_kernel,  cudaFuncAttributeMaxDynamicSharedMemorySize, RSMEM_BYTES);
        once = true;
    }

    const int EL = 256;

    // launch 0: input transpose/split
    transpose_split<<<(TB * HH + EL - 1) / EL, EL>>>(xpos, xcathi, xcatlo);

    // launch 1: merged prep (weights, biases, scheduler init)
    {
        int n = HH * HH + HH * KFC1 + 2 * LAYERS * G4H * HH + LAYERS * G4H + 1280;
        prep_all<<<(n + EL - 1) / EL, EL>>>(fc0_w, fc1_w, w_ih, w_hh, b_ih, b_hh,
                                            fc0whi, fc0wlo, fc1whi, fc1wlo,
                                            wihhi, wihlo, whhhi, whhlo, bcomb, sched);
    }

    // launch 2: fc0 -> x[0] (split store)
    gemm_bf16<1><<<dim3(HH / 128, TB / 128, 1), 256, SMEM_BYTES>>>(
        xcathi, xcatlo, fc0whi, fc0wlo, fc0_b,
        nullptr, xhi, xlo, TB, HH, HH, 1);

    // launch 3: dataflow-scheduled mega kernel (all layers, all steps)
    mega_kernel<<<LGRID, 256, RSMEM_BYTES>>>(
        xhi, xlo, wihhi, wihlo, whhhi, whhlo, bcomb, c, sched);

    // x[10] -> packed fc1 input
    pack_split<<<(BB * KFC1 + EL - 1) / EL, EL>>>(
        xhi + (size_t)10 * TB * HH, xlo + (size_t)10 * TB * HH, xcathi, xcatlo);

    // fc1 split-K partials + reduce
    gemm_bf16<4><<<dim3(HH / 128, BB / 128, SPLITK), 256, SMEM_BYTES>>>(
        xcathi, xcatlo, fc1whi, fc1wlo, nullptr,
        part, nullptr, nullptr, BB, HH, KFC1, SPLITK);
    reduce_fc1<<<(BB * HH + EL - 1) / EL, EL>>>(part, fc1_b, out);
}

// round 15
// speedup vs baseline: 1.6194x; 1.1324x over previous
#include <cuda_runtime.h>
#include <cuda_bf16.h>
#include <math.h>
#include <stdint.h>

#define HH 768
#define LAYERS 10
#define WW 10
#define BB 512
#define G4H 3072
#define TB 5120          // WW*BB
#define KFC1 (WW*HH)     // 7680
#define SPLITK 12

#define KT 32            // K-slab in elements
#define STRIDE 20        // u32 per smem row (16 used + 4 pad; ldmatrix conflict-free)
#define PLANE (128 * STRIDE)               // u32 per 128-row plane
#define SMEM_BYTES (2 * 4 * PLANE * 4)     // 81920 (128x128, 2-stage) — all kernels

#define LGRID 296        // 148 SMs x occ 2 — all co-resident
#define NBATCH 400       // LAYERS * WW * 4 chains
#define TPB 24           // tiles per batch (128x128)
#define NTICK (NBATCH * TPB)   // 9600

typedef __nv_bfloat16 bf16;

// ---------------- scratch (device globals; allocation-free rule) -------------
__device__ bf16  g_xhi[11 * TB * HH], g_xlo[11 * TB * HH];   // x[l][t][b][h], l=0..10
__device__ float g_c[LAYERS * BB * HH];                      // per-layer cell state
__device__ bf16  g_xcathi[BB * KFC1], g_xcatlo[BB * KFC1];   // fc0 input / fc1 packed
__device__ bf16  g_fc0whi[HH * HH],   g_fc0wlo[HH * HH];
__device__ bf16  g_fc1whi[HH * KFC1], g_fc1wlo[HH * KFC1];
__device__ bf16  g_wihhi[LAYERS * G4H * HH], g_wihlo[LAYERS * G4H * HH];
__device__ bf16  g_whhhi[LAYERS * G4H * HH], g_whhlo[LAYERS * G4H * HH];
__device__ float g_bcomb[LAYERS * G4H];
__device__ float g_part[SPLITK * BB * HH];
// sched: [0..399] done, [400..799] dep, [800..1199] readyq, [1200] ticket, [1201] qtail
__device__ int   g_sched[1280];

// ---------------- helpers ----------------------------------------------------
__device__ __forceinline__ void split1(float v, bf16& h, bf16& l)
{
    h = __float2bfloat16_rn(v);
    l = __float2bfloat16_rn(v - __bfloat162float(h));
}

__device__ __forceinline__ float sigm(float x) { return 1.0f / (1.0f + expf(-x)); }

__device__ __forceinline__ void cpasync16(void* dst, const void* src)
{
    uint32_t s = (uint32_t)__cvta_generic_to_shared(dst);
    asm volatile("cp.async.cg.shared.global [%0], [%1], 16;\n" :: "r"(s), "l"(src));
}
__device__ __forceinline__ void cp_commit() { asm volatile("cp.async.commit_group;\n"); }

__device__ __forceinline__ void mma_bf16(float* c, const uint32_t* a, const uint32_t* b)
{
    asm volatile(
        "mma.sync.aligned.m16n8k16.row.col.f32.bf16.bf16.f32 "
        "{%0,%1,%2,%3}, {%4,%5,%6,%7}, {%8,%9}, {%0,%1,%2,%3};"
        : "+f"(c[0]), "+f"(c[1]), "+f"(c[2]), "+f"(c[3])
        : "r"(a[0]), "r"(a[1]), "r"(a[2]), "r"(a[3]), "r"(b[0]), "r"(b[1]));
}

__device__ __forceinline__ void ldsm4(uint32_t* r, uint32_t saddr)
{
    asm volatile("ldmatrix.sync.aligned.m8n8.x4.shared.b16 {%0,%1,%2,%3}, [%4];"
                 : "=r"(r[0]), "=r"(r[1]), "=r"(r[2]), "=r"(r[3]) : "r"(saddr));
}

// ---------------- regular GEMM (128x128 tile, 2-stage, occ 2) ----------------
// MODE 1: (Chi,Clo) split bf16 = acc + bias     (fc0)
// MODE 4: raw fp32 partial store (split-K via blockIdx.z)  (fc1)
template <int MODE>
__global__ __launch_bounds__(256, 2) void gemm_bf16(
    const bf16* __restrict__ Ahi, const bf16* __restrict__ Alo,
    const bf16* __restrict__ Bhi, const bf16* __restrict__ Blo,
    const float* __restrict__ bias,
    float* __restrict__ Cf,
    bf16* __restrict__ Chi, bf16* __restrict__ Clo,
    int M, int N, int K, int nsplit)
{
    extern __shared__ uint32_t sm[];
    const int tid = threadIdx.x;
    const int lane = tid & 31;
    const int wid = tid >> 5;
    const int wm = wid >> 2;
    const int wn = wid & 3;
    const int bm = blockIdx.y * 128;
    const int bn = blockIdx.x * 128;
    const int q = lane >> 2;
    const int r = lane & 3;

    const int NS = K / KT;
    const int NSLABS = NS / nsplit;
    const int s0 = blockIdx.z * NSLABS;

    const int lrowA = ((lane >> 3) & 1) * 8 + (lane & 7);
    const int lchA  = (lane >> 4) & 1;
    const int lrowB = ((lane >> 4) & 1) * 8 + (lane & 7);
    const int lchB  = (lane >> 3) & 1;
    const uint32_t smem_b = (uint32_t)__cvta_generic_to_shared(sm);

    float acc[4][4][4];
#pragma unroll
    for (int i = 0; i < 4; i++)
#pragma unroll
        for (int j = 0; j < 4; j++)
#pragma unroll
            for (int v = 0; v < 4; v++) acc[i][j][v] = 0.f;

    auto issue = [&](int slab, int stage) {
        int k0 = slab * KT;
        uint32_t* base = sm + stage * 4 * PLANE;
#pragma unroll
        for (int i = 0; i < 2; i++) {
            int f = tid + i * 256;
            int m = f >> 2, cc = f & 3;
            size_t ga = (size_t)(bm + m) * K + k0 + cc * 8;
            size_t gb = (size_t)(bn + m) * K + k0 + cc * 8;
            int off = m * STRIDE + cc * 4;
            cpasync16(base + 0 * PLANE + off, Ahi + ga);
            cpasync16(base + 1 * PLANE + off, Alo + ga);
            cpasync16(base + 2 * PLANE + off, Bhi + gb);
            cpasync16(base + 3 * PLANE + off, Blo + gb);
        }
        cp_commit();
    };

    auto compute = [&](int stage) {
        uint32_t Ahb = smem_b + (stage * 4 + 0) * PLANE * 4;
        uint32_t Alb = smem_b + (stage * 4 + 1) * PLANE * 4;
        uint32_t Bhb = smem_b + (stage * 4 + 2) * PLANE * 4;
        uint32_t Blb = smem_b + (stage * 4 + 3) * PLANE * 4;
        uint32_t aoff = (uint32_t)((wm * 64 + lrowA) * STRIDE + lchA * 4) * 4;
        uint32_t boff = (uint32_t)((wn * 32 + lrowB) * STRIDE + lchB * 4) * 4;
#pragma unroll
        for (int k16 = 0; k16 < 2; k16++) {
            uint32_t kb = (uint32_t)(k16 * 8) * 4;
            uint32_t bh[4][2], bl[4][2];
#pragma unroll
            for (int p = 0; p < 2; p++) {
                uint32_t bo = boff + kb + (uint32_t)(p * 16 * STRIDE) * 4;
                uint32_t r4[4];
                ldsm4(r4, Bhb + bo);
                bh[p * 2][0] = r4[0]; bh[p * 2][1] = r4[1];
                bh[p * 2 + 1][0] = r4[2]; bh[p * 2 + 1][1] = r4[3];
                ldsm4(r4, Blb + bo);
                bl[p * 2][0] = r4[0]; bl[p * 2][1] = r4[1];
                bl[p * 2 + 1][0] = r4[2]; bl[p * 2 + 1][1] = r4[3];
            }
#pragma unroll
            for (int mi = 0; mi < 4; mi++) {
                uint32_t ao = aoff + kb + (uint32_t)(mi * 16 * STRIDE) * 4;
                uint32_t ah[4], al[4];
                ldsm4(ah, Ahb + ao);
#pragma unroll
                for (int ni = 0; ni < 4; ni++) {
                    mma_bf16(acc[mi][ni], ah, bh[ni]);
                    mma_bf16(acc[mi][ni], ah, bl[ni]);
                }
                ldsm4(al, Alb + ao);
#pragma unroll
                for (int ni = 0; ni < 4; ni++)
                    mma_bf16(acc[mi][ni], al, bh[ni]);
            }
        }
    };

    issue(s0, 0);
    if (NSLABS > 1) issue(s0 + 1, 1); else cp_commit();
    for (int s = 0; s < NSLABS; s++) {
        if (s + 1 < NSLABS) asm volatile("cp.async.wait_group 1;\n");
        else                asm volatile("cp.async.wait_group 0;\n");
        __syncthreads();
        compute(s & 1);
        __syncthreads();
        if (s + 2 < NSLABS) issue(s0 + s + 2, s & 1);
    }

#pragma unroll
    for (int mi = 0; mi < 4; mi++) {
#pragma unroll
        for (int ni = 0; ni < 4; ni++) {
            int m0 = bm + wm * 64 + mi * 16 + q;
            int n0 = bn + wn * 32 + ni * 8 + r * 2;
            float* a = acc[mi][ni];
            if (MODE == 1) {
                float bv0 = bias[n0], bv1 = bias[n0 + 1];
                float v00 = a[0] + bv0, v01 = a[1] + bv1;
                float v10 = a[2] + bv0, v11 = a[3] + bv1;
                bf16 h0, l0, h1, l1;
                split1(v00, h0, l0); split1(v01, h1, l1);
                *(__nv_bfloat162*)(Chi + (size_t)m0 * N + n0) = __nv_bfloat162(h0, h1);
                *(__nv_bfloat162*)(Clo + (size_t)m0 * N + n0) = __nv_bfloat162(l0, l1);
                split1(v10, h0, l0); split1(v11, h1, l1);
                *(__nv_bfloat162*)(Chi + (size_t)(m0 + 8) * N + n0) = __nv_bfloat162(h0, h1);
                *(__nv_bfloat162*)(Clo + (size_t)(m0 + 8) * N + n0) = __nv_bfloat162(l0, l1);
            } else {
                float* dst = Cf + ((size_t)blockIdx.z * M + m0) * N + n0;
                dst[0] = a[0]; dst[1] = a[1];
                dst += (size_t)8 * N;
                dst[0] = a[2]; dst[1] = a[3];
            }
        }
    }
}

// ---- dataflow-scheduled mega kernel: all 10 layers x 10 steps ---------------
// batch id = l*40 + t*4 + chain; 24 tiles (128x128) per batch; tile = fused
// (x[l][t]·wih^T + h[t-1]·whh^T) K=1536 GEMM + LSTM cell -> x[l+1][t].
__global__ __launch_bounds__(256, 2) void mega_kernel(
    bf16* __restrict__ xhi, bf16* __restrict__ xlo,
    const bf16* __restrict__ wihhi, const bf16* __restrict__ wihlo,
    const bf16* __restrict__ whhhi, const bf16* __restrict__ whhlo,
    const float* __restrict__ bcomb, float* __restrict__ call,
    int* __restrict__ sched)
{
    extern __shared__ uint32_t sm[];
    __shared__ int s_ticket, s_batch;
    const int tid = threadIdx.x;
    const int lane = tid & 31;
    const int wid = tid >> 5;
    const int wm = wid >> 2;
    const int wn = wid & 3;
    const int q = lane >> 2;
    const int r = lane & 3;

    const int lrowA = ((lane >> 3) & 1) * 8 + (lane & 7);
    const int lchA  = (lane >> 4) & 1;
    const int lrowB = ((lane >> 4) & 1) * 8 + (lane & 7);
    const int lchB  = (lane >> 3) & 1;
    const uint32_t smem_b = (uint32_t)__cvta_generic_to_shared(sm);

    int* done  = sched;
    int* dep   = sched + 400;
    int* rq    = sched + 800;

    for (;;) {
        if (tid == 0) s_ticket = atomicAdd(&sched[1200], 1);
        __syncthreads();
        int ticket = s_ticket;
        if (ticket >= NTICK) break;
        int slot = ticket / TPB;
        int bn = (ticket % TPB) * 128;
        if (tid == 0) {
            int b;
            while ((b = __ldcg(&rq[slot])) < 0) __nanosleep(100);
            s_batch = b;
        }
        __syncthreads();
        int batch = s_batch;
        int ch = batch & 3;
        int t  = (batch >> 2) % 10;
        int l  = batch / 40;
        int bm = ch * 128;

        const bf16* A1h = xhi + ((size_t)l * WW + t) * BB * HH;
        const bf16* A1l = xlo + ((size_t)l * WW + t) * BB * HH;
        const bf16* A2h = xhi + ((size_t)(l + 1) * WW + (t - 1)) * BB * HH;
        const bf16* A2l = xlo + ((size_t)(l + 1) * WW + (t - 1)) * BB * HH;
        const bf16* B1h = wihhi + (size_t)l * G4H * HH;
        const bf16* B1l = wihlo + (size_t)l * G4H * HH;
        const bf16* B2h = whhhi + (size_t)l * G4H * HH;
        const bf16* B2l = whhlo + (size_t)l * G4H * HH;
        const int NSLAB = t ? 48 : 24;

        float acc[4][4][4];
#pragma unroll
        for (int i = 0; i < 4; i++)
#pragma unroll
            for (int j = 0; j < 4; j++)
#pragma unroll
                for (int v = 0; v < 4; v++) acc[i][j][v] = 0.f;

        auto issue = [&](int slab, int stage) {
            int seg2 = slab >= 24;
            int k0 = (seg2 ? slab - 24 : slab) * KT;
            const bf16* Ah = seg2 ? A2h : A1h;
            const bf16* Al = seg2 ? A2l : A1l;
            const bf16* Bh = seg2 ? B2h : B1h;
            const bf16* Bl = seg2 ? B2l : B1l;
            uint32_t* base = sm + stage * 4 * PLANE;
#pragma unroll
            for (int i = 0; i < 2; i++) {
                int f = tid + i * 256;
                int m = f >> 2, cc = f & 3;
                size_t ga = (size_t)(bm + m) * HH + k0 + cc * 8;
                size_t gb = (size_t)(bn + m) * HH + k0 + cc * 8;
                int off = m * STRIDE + cc * 4;
                cpasync16(base + 0 * PLANE + off, Ah + ga);
                cpasync16(base + 1 * PLANE + off, Al + ga);
                cpasync16(base + 2 * PLANE + off, Bh + gb);
                cpasync16(base + 3 * PLANE + off, Bl + gb);
            }
            cp_commit();
        };

        auto compute = [&](int stage) {
            uint32_t Ahb = smem_b + (stage * 4 + 0) * PLANE * 4;
            uint32_t Alb = smem_b + (stage * 4 + 1) * PLANE * 4;
            uint32_t Bhb = smem_b + (stage * 4 + 2) * PLANE * 4;
            uint32_t Blb = smem_b + (stage * 4 + 3) * PLANE * 4;
            uint32_t aoff = (uint32_t)((wm * 64 + lrowA) * STRIDE + lchA * 4) * 4;
            uint32_t boff = (uint32_t)((wn * 32 + lrowB) * STRIDE + lchB * 4) * 4;
#pragma unroll
            for (int k16 = 0; k16 < 2; k16++) {
                uint32_t kb = (uint32_t)(k16 * 8) * 4;
                uint32_t bh[4][2], bl[4][2];
#pragma unroll
                for (int p = 0; p < 2; p++) {
                    uint32_t bo = boff + kb + (uint32_t)(p * 16 * STRIDE) * 4;
                    uint32_t r4[4];
                    ldsm4(r4, Bhb + bo);
                    bh[p * 2][0] = r4[0]; bh[p * 2][1] = r4[1];
                    bh[p * 2 + 1][0] = r4[2]; bh[p * 2 + 1][1] = r4[3];
                    ldsm4(r4, Blb + bo);
                    bl[p * 2][0] = r4[0]; bl[p * 2][1] = r4[1];
                    bl[p * 2 + 1][0] = r4[2]; bl[p * 2 + 1][1] = r4[3];
                }
#pragma unroll
                for (int mi = 0; mi < 4; mi++) {
                    uint32_t ao = aoff + kb + (uint32_t)(mi * 16 * STRIDE) * 4;
                    uint32_t ah[4], al[4];
                    ldsm4(ah, Ahb + ao);
#pragma unroll
                    for (int ni = 0; ni < 4; ni++) {
                        mma_bf16(acc[mi][ni], ah, bh[ni]);
                        mma_bf16(acc[mi][ni], ah, bl[ni]);
                    }
                    ldsm4(al, Alb + ao);
#pragma unroll
                    for (int ni = 0; ni < 4; ni++)
                        mma_bf16(acc[mi][ni], al, bh[ni]);
                }
            }
        };

        issue(0, 0);
        issue(1, 1);
        for (int s = 0; s < NSLAB; s++) {
            if (s + 1 < NSLAB) asm volatile("cp.async.wait_group 1;\n");
            else               asm volatile("cp.async.wait_group 0;\n");
            __syncthreads();
            compute(s & 1);
            __syncthreads();
            if (s + 2 < NSLAB) issue(s + 2, s & 1);
        }

        // ---- LSTM cell epilogue -> x[l+1][t] ----
        {
            const float* bias = bcomb + (size_t)l * G4H;
            float* cst = call + (size_t)l * BB * HH;
            bf16* Chi = xhi + ((size_t)(l + 1) * WW + t) * BB * HH;
            bf16* Clo = xlo + ((size_t)(l + 1) * WW + t) * BB * HH;
#pragma unroll
            for (int mi = 0; mi < 4; mi++) {
#pragma unroll
                for (int ni = 0; ni < 4; ni++) {
                    int m0 = bm + wm * 64 + mi * 16 + q;
                    int n0 = bn + wn * 32 + ni * 8 + r * 2;
                    float* a = acc[mi][ni];
                    float bv0 = bias[n0], bv1 = bias[n0 + 1];
                    float a0 = a[0] + bv0, a1 = a[1] + bv1;
                    float a2 = a[2] + bv0, a3 = a[3] + bv1;
                    float p0 = __shfl_xor_sync(0xFFFFFFFFu, a0, 1);
                    float p1 = __shfl_xor_sync(0xFFFFFFFFu, a1, 1);
                    float p2 = __shfl_xor_sync(0xFFFFFFFFu, a2, 1);
                    float p3 = __shfl_xor_sync(0xFFFFFFFFu, a3, 1);
                    if ((r & 1) == 0) {
                        int n = n0 >> 2;
#pragma unroll
                        for (int rr = 0; rr < 2; rr++) {
                            int m = m0 + rr * 8;
                            float gi = rr ? a2 : a0;
                            float gf = rr ? a3 : a1;
                            float gg = rr ? p2 : p0;
                            float go = rr ? p3 : p1;
                            float cn;
                            if (t == 0) {
                                cn = sigm(gi) * tanhf(gg);
                            } else {
                                float cold = __ldcg(cst + (size_t)m * HH + n);
                                cn = sigm(gf) * cold + sigm(gi) * tanhf(gg);
                            }
                            __stcg(cst + (size_t)m * HH + n, cn);
                            float h = sigm(go) * tanhf(cn);
                            bf16 hh, hl;
                            split1(h, hh, hl);
                            Chi[(size_t)m * HH + n] = hh;
                            Clo[(size_t)m * HH + n] = hl;
                        }
                    }
                }
            }
        }

        // ---- publish completion ----
        __threadfence();
        __syncthreads();
        if (tid == 0) {
            if (atomicAdd(&done[batch], 1) == TPB - 1) {
                if (l < LAYERS - 1) {
                    if (atomicSub(&dep[batch + 40], 1) == 1) {
                        int p = atomicAdd(&sched[1201], 1);
                        __stcg(&rq[p], batch + 40);
                    }
                }
                if (t < WW - 1) {
                    if (atomicSub(&dep[batch + 4], 1) == 1) {
                        int p = atomicAdd(&sched[1201], 1);
                        __stcg(&rq[p], batch + 4);
                    }
                }
            }
        }
    }
}

// ---------------- prep (merged): weight splits + bias + scheduler init -------
__global__ void prep_all(const float* __restrict__ fc0_w, const float* __restrict__ fc1_w,
                         const float* __restrict__ wih, const float* __restrict__ whh,
                         const float* __restrict__ bih, const float* __restrict__ bhh,
                         bf16* __restrict__ f0h, bf16* __restrict__ f0l,
                         bf16* __restrict__ f1h, bf16* __restrict__ f1l,
                         bf16* __restrict__ ihh, bf16* __restrict__ ihl,
                         bf16* __restrict__ hhh, bf16* __restrict__ hhl,
                         float* __restrict__ bc, int* __restrict__ sched)
{
    int i = blockIdx.x * blockDim.x + threadIdx.x;
    const int NA = HH * HH;
    const int NB = NA + HH * KFC1;
    const int NP = 2 * LAYERS * G4H * HH;
    if (i < NA) { split1(fc0_w[i], f0h[i], f0l[i]); return; }
    if (i < NB) { int j = i - NA; split1(fc1_w[j], f1h[j], f1l[j]); return; }
    int i2 = i - NB;
    if (i2 < NP) {
        int sel = i2 >= NP / 2;
        int ii = sel ? i2 - NP / 2 : i2;
        int k = ii % HH;
        int j = (ii / HH) % G4H;
        int l = ii / (HH * G4H);
        int n = j >> 2, g = j & 3;
        const float* src = sel ? whh : wih;
        float v = src[(size_t)l * G4H * HH + (size_t)(g * HH + n) * HH + k];
        if (sel) split1(v, hhh[ii], hhl[ii]);
        else     split1(v, ihh[ii], ihl[ii]);
        return;
    }
    int i3 = i2 - NP;
    if (i3 < LAYERS * G4H) {
        int j = i3 % G4H;
        int l = i3 / G4H;
        int n = j >> 2, g = j & 3;
        bc[i3] = bih[l * G4H + g * HH + n] + bhh[l * G4H + g * HH + n];
        return;
    }
    int i4 = i3 - LAYERS * G4H;
    if (i4 < 1280) {
        if (i4 < 400) sched[i4] = 0;                       // done
        else if (i4 < 800) {                               // dep
            int b = i4 - 400;
            int l = b / 40, tt = (b % 40) >> 2;
            sched[i4] = (l > 0 ? 1 : 0) + (tt > 0 ? 1 : 0);
        } else if (i4 < 1200) {                            // readyq
            int s = i4 - 800;
            sched[i4] = (s < 4) ? s : -1;                  // batches (l=0,t=0,c=0..3)
        } else if (i4 == 1200) sched[i4] = 0;              // ticket
        else sched[i4] = 4;                                // qtail
    }
}

// (B,W,H) fp32 -> (W*B, H) split bf16
__global__ void transpose_split(const float* __restrict__ src,
                                bf16* __restrict__ hi, bf16* __restrict__ lo)
{
    int i = blockIdx.x * blockDim.x + threadIdx.x;
    if (i >= TB * HH) return;
    int k = i % HH;
    int row = i / HH;
    int t = row / BB, b = row % BB;
    split1(src[((size_t)b * WW + t) * HH + k], hi[i], lo[i]);
}

// (W,B,H) split -> (B, W*H) split
__global__ void pack_split(const bf16* __restrict__ xhi, const bf16* __restrict__ xlo,
                           bf16* __restrict__ chi, bf16* __restrict__ clo)
{
    int i = blockIdx.x * blockDim.x + threadIdx.x;
    if (i >= BB * KFC1) return;
    int b = i / KFC1;
    int tk = i % KFC1;
    int t = tk / HH, k = tk % HH;
    size_t s = ((size_t)t * BB + b) * HH + k;
    chi[i] = xhi[s];
    clo[i] = xlo[s];
}

__global__ void reduce_fc1(const float* __restrict__ part, const float* __restrict__ b,
                           float* __restrict__ out)
{
    int i = blockIdx.x * blockDim.x + threadIdx.x;
    if (i >= BB * HH) return;
    float s = b[i % HH];
#pragma unroll
    for (int z = 0; z < SPLITK; z++) s += part[(size_t)z * BB * HH + i];
    out[i] = s;
}

// ---------------- host -------------------------------------------------------
extern "C" void kernel_launch(void* const* d_in, const int* in_sizes, int n_in,
                              void* d_out, int out_size)
{
    const float* xpos  = (const float*)d_in[0];
    const float* fc0_w = (const float*)d_in[1];
    const float* fc0_b = (const float*)d_in[2];
    const float* w_ih  = (const float*)d_in[3];
    const float* w_hh  = (const float*)d_in[4];
    const float* b_ih  = (const float*)d_in[5];
    const float* b_hh  = (const float*)d_in[6];
    const float* fc1_w = (const float*)d_in[7];
    const float* fc1_b = (const float*)d_in[8];
    float* out = (float*)d_out;

    bf16 *xhi, *xlo, *xcathi, *xcatlo;
    bf16 *fc0whi, *fc0wlo, *fc1whi, *fc1wlo, *wihhi, *wihlo, *whhhi, *whhlo;
    float *c, *bcomb, *part;
    int* sched;
    cudaGetSymbolAddress((void**)&xhi,   g_xhi);
    cudaGetSymbolAddress((void**)&xlo,   g_xlo);
    cudaGetSymbolAddress((void**)&xcathi, g_xcathi);
    cudaGetSymbolAddress((void**)&xcatlo, g_xcatlo);
    cudaGetSymbolAddress((void**)&fc0whi, g_fc0whi);
    cudaGetSymbolAddress((void**)&fc0wlo, g_fc0wlo);
    cudaGetSymbolAddress((void**)&fc1whi, g_fc1whi);
    cudaGetSymbolAddress((void**)&fc1wlo, g_fc1wlo);
    cudaGetSymbolAddress((void**)&wihhi, g_wihhi);
    cudaGetSymbolAddress((void**)&wihlo, g_wihlo);
    cudaGetSymbolAddress((void**)&whhhi, g_whhhi);
    cudaGetSymbolAddress((void**)&whhlo, g_whhlo);
    cudaGetSymbolAddress((void**)&c,     g_c);
    cudaGetSymbolAddress((void**)&bcomb, g_bcomb);
    cudaGetSymbolAddress((void**)&part,  g_part);
    cudaGetSymbolAddress((void**)&sched, g_sched);

    static bool once = false;
    if (!once) {
        cudaFuncSetAttribute(gemm_bf16<1>, cudaFuncAttributeMaxDynamicSharedMemorySize, SMEM_BYTES);
        cudaFuncSetAttribute(gemm_bf16<4>, cudaFuncAttributeMaxDynamicSharedMemorySize, SMEM_BYTES);
        cudaFuncSetAttribute(mega_kernel,  cudaFuncAttributeMaxDynamicSharedMemorySize, SMEM_BYTES);
        once = true;
    }

    const int EL = 256;

    // launch 0: input transpose/split
    transpose_split<<<(TB * HH + EL - 1) / EL, EL>>>(xpos, xcathi, xcatlo);

    // launch 1: merged prep (weights, biases, scheduler init)
    {
        int n = HH * HH + HH * KFC1 + 2 * LAYERS * G4H * HH + LAYERS * G4H + 1280;
        prep_all<<<(n + EL - 1) / EL, EL>>>(fc0_w, fc1_w, w_ih, w_hh, b_ih, b_hh,
                                            fc0whi, fc0wlo, fc1whi, fc1wlo,
                                            wihhi, wihlo, whhhi, whhlo, bcomb, sched);
    }

    // launch 2: fc0 -> x[0] (split store)
    gemm_bf16<1><<<dim3(HH / 128, TB / 128, 1), 256, SMEM_BYTES>>>(
        xcathi, xcatlo, fc0whi, fc0wlo, fc0_b,
        nullptr, xhi, xlo, TB, HH, HH, 1);

    // launch 3: dataflow-scheduled mega kernel (all layers, all steps)
    mega_kernel<<<LGRID, 256, SMEM_BYTES>>>(
        xhi, xlo, wihhi, wihlo, whhhi, whhlo, bcomb, c, sched);

    // x[10] -> packed fc1 input
    pack_split<<<(BB * KFC1 + EL - 1) / EL, EL>>>(
        xhi + (size_t)10 * TB * HH, xlo + (size_t)10 * TB * HH, xcathi, xcatlo);

    // fc1 split-K partials + reduce
    gemm_bf16<4><<<dim3(HH / 128, BB / 128, SPLITK), 256, SMEM_BYTES>>>(
        xcathi, xcatlo, fc1whi, fc1wlo, nullptr,
        part, nullptr, nullptr, BB, HH, KFC1, SPLITK);
    reduce_fc1<<<(BB * HH + EL - 1) / EL, EL>>>(part, fc1_b, out);
}

// round 16
// speedup vs baseline: 1.6762x; 1.0351x over previous
#include <cuda_runtime.h>
#include <cuda_bf16.h>
#include <math.h>
#include <stdint.h>

#define HH 768
#define LAYERS 10
#define WW 10
#define BB 512
#define G4H 3072
#define TB 5120          // WW*BB
#define KFC1 (WW*HH)     // 7680
#define SPLITK 12

#define KT 32            // K-slab in elements
#define STRIDE 20        // u32 per smem row (16 used + 4 pad; ldmatrix conflict-free)
#define PLANE (128 * STRIDE)               // u32 per 128-row plane
#define SMEM_BYTES (2 * 4 * PLANE * 4)     // 81920 (128x128, 2-stage)

#define LGRID 296        // 148 SMs x occ 2 — all co-resident
#define NBATCH 400       // LSTM batches: l*40 + t*4 + chain
#define TPB 24           // tiles per LSTM batch (128x128)
#define NFC0 240         // fc0 tiles (40 sextets)
#define NTICK (NFC0 + NBATCH * TPB)   // 9840

typedef __nv_bfloat16 bf16;

// ---------------- scratch (device globals; allocation-free rule) -------------
__device__ bf16  g_xhi[11 * TB * HH], g_xlo[11 * TB * HH];   // x[l][t][b][h], l=0..10
__device__ float g_c[LAYERS * BB * HH];                      // per-layer cell state
__device__ bf16  g_xcathi[BB * KFC1], g_xcatlo[BB * KFC1];   // fc0 input / fc1 packed
__device__ bf16  g_fc0whi[HH * HH],   g_fc0wlo[HH * HH];
__device__ bf16  g_fc1whi[HH * KFC1], g_fc1wlo[HH * KFC1];
__device__ bf16  g_wihhi[LAYERS * G4H * HH], g_wihlo[LAYERS * G4H * HH];
__device__ bf16  g_whhhi[LAYERS * G4H * HH], g_whhlo[LAYERS * G4H * HH];
__device__ float g_bcomb[LAYERS * G4H];
__device__ float g_part[SPLITK * BB * HH];
// sched: [0..439] done (400 LSTM + 40 fc0), [440..839] dep, [840..1239] readyq,
//        [1240] ticket, [1241] qtail
__device__ int   g_sched[1280];

// ---------------- helpers ----------------------------------------------------
__device__ __forceinline__ void split1(float v, bf16& h, bf16& l)
{
    h = __float2bfloat16_rn(v);
    l = __float2bfloat16_rn(v - __bfloat162float(h));
}

__device__ __forceinline__ float sigm(float x) { return 1.0f / (1.0f + expf(-x)); }

__device__ __forceinline__ void cpasync16(void* dst, const void* src)
{
    uint32_t s = (uint32_t)__cvta_generic_to_shared(dst);
    asm volatile("cp.async.cg.shared.global [%0], [%1], 16;\n" :: "r"(s), "l"(src));
}
__device__ __forceinline__ void cp_commit() { asm volatile("cp.async.commit_group;\n"); }

__device__ __forceinline__ void mma_bf16(float* c, const uint32_t* a, const uint32_t* b)
{
    asm volatile(
        "mma.sync.aligned.m16n8k16.row.col.f32.bf16.bf16.f32 "
        "{%0,%1,%2,%3}, {%4,%5,%6,%7}, {%8,%9}, {%0,%1,%2,%3};"
        : "+f"(c[0]), "+f"(c[1]), "+f"(c[2]), "+f"(c[3])
        : "r"(a[0]), "r"(a[1]), "r"(a[2]), "r"(a[3]), "r"(b[0]), "r"(b[1]));
}

__device__ __forceinline__ void ldsm4(uint32_t* r, uint32_t saddr)
{
    asm volatile("ldmatrix.sync.aligned.m8n8.x4.shared.b16 {%0,%1,%2,%3}, [%4];"
                 : "=r"(r[0]), "=r"(r[1]), "=r"(r[2]), "=r"(r[3]) : "r"(saddr));
}

// compute one k16 with RAW-free ordering: hh sweep, hl sweep, lh sweep.
// (per-accumulator order hh->hl->lh unchanged => bit-identical numerics)
#define K16_COMPUTE(Ahb, Alb, aoff, kb, bh, bl, acc) \
    _Pragma("unroll") \
    for (int mi = 0; mi < 4; mi++) { \
        uint32_t ao = (aoff) + (kb) + (uint32_t)(mi * 16 * STRIDE) * 4; \
        uint32_t ah[4], al[4]; \
        ldsm4(ah, (Ahb) + ao); \
        ldsm4(al, (Alb) + ao); \
        _Pragma("unroll") \
        for (int ni = 0; ni < 4; ni++) mma_bf16(acc[mi][ni], ah, bh[ni]); \
        _Pragma("unroll") \
        for (int ni = 0; ni < 4; ni++) mma_bf16(acc[mi][ni], ah, bl[ni]); \
        _Pragma("unroll") \
        for (int ni = 0; ni < 4; ni++) mma_bf16(acc[mi][ni], al, bh[ni]); \
    }

// ---------------- regular GEMM (128x128 tile, 2-stage, occ 2) ----------------
// MODE 4: raw fp32 partial store (split-K via blockIdx.z)  (fc1)
template <int MODE>
__global__ __launch_bounds__(256, 2) void gemm_bf16(
    const bf16* __restrict__ Ahi, const bf16* __restrict__ Alo,
    const bf16* __restrict__ Bhi, const bf16* __restrict__ Blo,
    float* __restrict__ Cf,
    int M, int N, int K, int nsplit)
{
    extern __shared__ uint32_t sm[];
    const int tid = threadIdx.x;
    const int lane = tid & 31;
    const int wid = tid >> 5;
    const int wm = wid >> 2;
    const int wn = wid & 3;
    const int bm = blockIdx.y * 128;
    const int bn = blockIdx.x * 128;
    const int q = lane >> 2;
    const int r = lane & 3;

    const int NS = K / KT;
    const int NSLABS = NS / nsplit;
    const int s0 = blockIdx.z * NSLABS;

    const int lrowA = ((lane >> 3) & 1) * 8 + (lane & 7);
    const int lchA  = (lane >> 4) & 1;
    const int lrowB = ((lane >> 4) & 1) * 8 + (lane & 7);
    const int lchB  = (lane >> 3) & 1;
    const uint32_t smem_b = (uint32_t)__cvta_generic_to_shared(sm);

    float acc[4][4][4];
#pragma unroll
    for (int i = 0; i < 4; i++)
#pragma unroll
        for (int j = 0; j < 4; j++)
#pragma unroll
            for (int v = 0; v < 4; v++) acc[i][j][v] = 0.f;

    auto issue = [&](int slab, int stage) {
        int k0 = slab * KT;
        uint32_t* base = sm + stage * 4 * PLANE;
#pragma unroll
        for (int i = 0; i < 2; i++) {
            int f = tid + i * 256;
            int m = f >> 2, cc = f & 3;
            size_t ga = (size_t)(bm + m) * K + k0 + cc * 8;
            size_t gb = (size_t)(bn + m) * K + k0 + cc * 8;
            int off = m * STRIDE + cc * 4;
            cpasync16(base + 0 * PLANE + off, Ahi + ga);
            cpasync16(base + 1 * PLANE + off, Alo + ga);
            cpasync16(base + 2 * PLANE + off, Bhi + gb);
            cpasync16(base + 3 * PLANE + off, Blo + gb);
        }
        cp_commit();
    };

    auto compute = [&](int stage) {
        uint32_t Ahb = smem_b + (stage * 4 + 0) * PLANE * 4;
        uint32_t Alb = smem_b + (stage * 4 + 1) * PLANE * 4;
        uint32_t Bhb = smem_b + (stage * 4 + 2) * PLANE * 4;
        uint32_t Blb = smem_b + (stage * 4 + 3) * PLANE * 4;
        uint32_t aoff = (uint32_t)((wm * 64 + lrowA) * STRIDE + lchA * 4) * 4;
        uint32_t boff = (uint32_t)((wn * 32 + lrowB) * STRIDE + lchB * 4) * 4;
#pragma unroll
        for (int k16 = 0; k16 < 2; k16++) {
            uint32_t kb = (uint32_t)(k16 * 8) * 4;
            uint32_t bh[4][2], bl[4][2];
#pragma unroll
            for (int p = 0; p < 2; p++) {
                uint32_t bo = boff + kb + (uint32_t)(p * 16 * STRIDE) * 4;
                uint32_t r4[4];
                ldsm4(r4, Bhb + bo);
                bh[p * 2][0] = r4[0]; bh[p * 2][1] = r4[1];
                bh[p * 2 + 1][0] = r4[2]; bh[p * 2 + 1][1] = r4[3];
                ldsm4(r4, Blb + bo);
                bl[p * 2][0] = r4[0]; bl[p * 2][1] = r4[1];
                bl[p * 2 + 1][0] = r4[2]; bl[p * 2 + 1][1] = r4[3];
            }
            K16_COMPUTE(Ahb, Alb, aoff, kb, bh, bl, acc)
        }
    };

    issue(s0, 0);
    if (NSLABS > 1) issue(s0 + 1, 1); else cp_commit();
    for (int s = 0; s < NSLABS; s++) {
        if (s + 1 < NSLABS) asm volatile("cp.async.wait_group 1;\n");
        else                asm volatile("cp.async.wait_group 0;\n");
        __syncthreads();
        compute(s & 1);
        __syncthreads();
        if (s + 2 < NSLABS) issue(s0 + s + 2, s & 1);
    }

#pragma unroll
    for (int mi = 0; mi < 4; mi++) {
#pragma unroll
        for (int ni = 0; ni < 4; ni++) {
            int m0 = bm + wm * 64 + mi * 16 + q;
            int n0 = bn + wn * 32 + ni * 8 + r * 2;
            float* a = acc[mi][ni];
            float* dst = Cf + ((size_t)blockIdx.z * M + m0) * N + n0;
            dst[0] = a[0]; dst[1] = a[1];
            dst += (size_t)8 * N;
            dst[0] = a[2]; dst[1] = a[3];
        }
    }
}

// ---- dataflow-scheduled mega kernel: fc0 + all 10 layers x 10 steps ---------
// ticket < 240: fc0 tile (dep-free). Else LSTM tile via ready-queue.
// LSTM batch id = l*40 + t*4 + chain; 24 tiles; tile = fused
// (x[l][t]·wih^T + h[t-1]·whh^T) K=1536 GEMM + LSTM cell -> x[l+1][t].
__global__ __launch_bounds__(256, 2) void mega_kernel(
    bf16* __restrict__ xhi, bf16* __restrict__ xlo,
    const bf16* __restrict__ xcathi, const bf16* __restrict__ xcatlo,
    const bf16* __restrict__ fc0whi, const bf16* __restrict__ fc0wlo,
    const float* __restrict__ fc0b,
    const bf16* __restrict__ wihhi, const bf16* __restrict__ wihlo,
    const bf16* __restrict__ whhhi, const bf16* __restrict__ whhlo,
    const float* __restrict__ bcomb, float* __restrict__ call,
    int* __restrict__ sched)
{
    extern __shared__ uint32_t sm[];
    __shared__ int s_ticket, s_batch;
    const int tid = threadIdx.x;
    const int lane = tid & 31;
    const int wid = tid >> 5;
    const int wm = wid >> 2;
    const int wn = wid & 3;
    const int q = lane >> 2;
    const int r = lane & 3;

    const int lrowA = ((lane >> 3) & 1) * 8 + (lane & 7);
    const int lchA  = (lane >> 4) & 1;
    const int lrowB = ((lane >> 4) & 1) * 8 + (lane & 7);
    const int lchB  = (lane >> 3) & 1;
    const uint32_t smem_b = (uint32_t)__cvta_generic_to_shared(sm);

    int* done  = sched;          // [0..439]
    int* dep   = sched + 440;    // [0..399]
    int* rq    = sched + 840;    // [0..399]

    for (;;) {
        if (tid == 0) s_ticket = atomicAdd(&sched[1240], 1);
        __syncthreads();
        int ticket = s_ticket;
        if (ticket >= NTICK) break;

        // ---- decode work item ----
        int isfc0 = ticket < NFC0;
        int bm, bn, t, l, ch, NSLAB, fcb;
        const bf16 *A1h, *A1l, *A2h, *A2l, *B1h, *B1l, *B2h, *B2l;
        if (isfc0) {
            fcb = ticket / 6;               // sextet 0..39  (t*4+ch)
            int cn = ticket % 6;
            t = fcb >> 2; ch = fcb & 3; l = 0;
            bm = t * BB + ch * 128;
            bn = cn * 128;
            NSLAB = 24;
            A1h = xcathi; A1l = xcatlo;
            B1h = fc0whi; B1l = fc0wlo;
            A2h = A1h; A2l = A1l; B2h = B1h; B2l = B1l;   // unused
        } else {
            int tk = ticket - NFC0;
            int slot = tk / TPB;
            bn = (tk % TPB) * 128;
            if (tid == 0) {
                int b;
                while ((b = __ldcg(&rq[slot])) < 0) __nanosleep(100);
                s_batch = b;
            }
            __syncthreads();
            int batch = s_batch;
            ch = batch & 3;
            t  = (batch >> 2) % 10;
            l  = batch / 40;
            bm = ch * 128;
            fcb = batch;
            A1h = xhi + ((size_t)l * WW + t) * BB * HH;
            A1l = xlo + ((size_t)l * WW + t) * BB * HH;
            A2h = xhi + ((size_t)(l + 1) * WW + (t - 1)) * BB * HH;
            A2l = xlo + ((size_t)(l + 1) * WW + (t - 1)) * BB * HH;
            B1h = wihhi + (size_t)l * G4H * HH;
            B1l = wihlo + (size_t)l * G4H * HH;
            B2h = whhhi + (size_t)l * G4H * HH;
            B2l = whhlo + (size_t)l * G4H * HH;
            NSLAB = t ? 48 : 24;
        }

        float acc[4][4][4];
#pragma unroll
        for (int i = 0; i < 4; i++)
#pragma unroll
            for (int j = 0; j < 4; j++)
#pragma unroll
                for (int v = 0; v < 4; v++) acc[i][j][v] = 0.f;

        auto issue = [&](int slab, int stage) {
            int seg2 = slab >= 24;
            int k0 = (seg2 ? slab - 24 : slab) * KT;
            const bf16* Ah = seg2 ? A2h : A1h;
            const bf16* Al = seg2 ? A2l : A1l;
            const bf16* Bh = seg2 ? B2h : B1h;
            const bf16* Bl = seg2 ? B2l : B1l;
            uint32_t* base = sm + stage * 4 * PLANE;
#pragma unroll
            for (int i = 0; i < 2; i++) {
                int f = tid + i * 256;
                int m = f >> 2, cc = f & 3;
                size_t ga = (size_t)(bm + m) * HH + k0 + cc * 8;
                size_t gb = (size_t)(bn + m) * HH + k0 + cc * 8;
                int off = m * STRIDE + cc * 4;
                cpasync16(base + 0 * PLANE + off, Ah + ga);
                cpasync16(base + 1 * PLANE + off, Al + ga);
                cpasync16(base + 2 * PLANE + off, Bh + gb);
                cpasync16(base + 3 * PLANE + off, Bl + gb);
            }
            cp_commit();
        };

        auto compute = [&](int stage) {
            uint32_t Ahb = smem_b + (stage * 4 + 0) * PLANE * 4;
            uint32_t Alb = smem_b + (stage * 4 + 1) * PLANE * 4;
            uint32_t Bhb = smem_b + (stage * 4 + 2) * PLANE * 4;
            uint32_t Blb = smem_b + (stage * 4 + 3) * PLANE * 4;
            uint32_t aoff = (uint32_t)((wm * 64 + lrowA) * STRIDE + lchA * 4) * 4;
            uint32_t boff = (uint32_t)((wn * 32 + lrowB) * STRIDE + lchB * 4) * 4;
#pragma unroll
            for (int k16 = 0; k16 < 2; k16++) {
                uint32_t kb = (uint32_t)(k16 * 8) * 4;
                uint32_t bh[4][2], bl[4][2];
#pragma unroll
                for (int p = 0; p < 2; p++) {
                    uint32_t bo = boff + kb + (uint32_t)(p * 16 * STRIDE) * 4;
                    uint32_t r4[4];
                    ldsm4(r4, Bhb + bo);
                    bh[p * 2][0] = r4[0]; bh[p * 2][1] = r4[1];
                    bh[p * 2 + 1][0] = r4[2]; bh[p * 2 + 1][1] = r4[3];
                    ldsm4(r4, Blb + bo);
                    bl[p * 2][0] = r4[0]; bl[p * 2][1] = r4[1];
                    bl[p * 2 + 1][0] = r4[2]; bl[p * 2 + 1][1] = r4[3];
                }
                K16_COMPUTE(Ahb, Alb, aoff, kb, bh, bl, acc)
            }
        };

        issue(0, 0);
        issue(1, 1);
        for (int s = 0; s < NSLAB; s++) {
            if (s + 1 < NSLAB) asm volatile("cp.async.wait_group 1;\n");
            else               asm volatile("cp.async.wait_group 0;\n");
            __syncthreads();
            compute(s & 1);
            __syncthreads();
            if (s + 2 < NSLAB) issue(s + 2, s & 1);
        }

        // ---- epilogue ----
        if (isfc0) {
            // split-store x[0]: rows bm.., cols bn.., N=HH
#pragma unroll
            for (int mi = 0; mi < 4; mi++) {
#pragma unroll
                for (int ni = 0; ni < 4; ni++) {
                    int m0 = bm + wm * 64 + mi * 16 + q;
                    int n0 = bn + wn * 32 + ni * 8 + r * 2;
                    float* a = acc[mi][ni];
                    float bv0 = fc0b[n0], bv1 = fc0b[n0 + 1];
                    float v00 = a[0] + bv0, v01 = a[1] + bv1;
                    float v10 = a[2] + bv0, v11 = a[3] + bv1;
                    bf16 h0, l0, h1, l1;
                    split1(v00, h0, l0); split1(v01, h1, l1);
                    *(__nv_bfloat162*)(xhi + (size_t)m0 * HH + n0) = __nv_bfloat162(h0, h1);
                    *(__nv_bfloat162*)(xlo + (size_t)m0 * HH + n0) = __nv_bfloat162(l0, l1);
                    split1(v10, h0, l0); split1(v11, h1, l1);
                    *(__nv_bfloat162*)(xhi + (size_t)(m0 + 8) * HH + n0) = __nv_bfloat162(h0, h1);
                    *(__nv_bfloat162*)(xlo + (size_t)(m0 + 8) * HH + n0) = __nv_bfloat162(l0, l1);
                }
            }
            __threadfence();
            __syncthreads();
            if (tid == 0) {
                if (atomicAdd(&done[400 + fcb], 1) == 5) {
                    if (atomicSub(&dep[fcb], 1) == 1) {        // LSTM (0,t,ch) = fcb
                        int p = atomicAdd(&sched[1241], 1);
                        __stcg(&rq[p], fcb);
                    }
                }
            }
        } else {
            const float* bias = bcomb + (size_t)l * G4H;
            float* cst = call + (size_t)l * BB * HH;
            bf16* Chi = xhi + ((size_t)(l + 1) * WW + t) * BB * HH;
            bf16* Clo = xlo + ((size_t)(l + 1) * WW + t) * BB * HH;
#pragma unroll
            for (int mi = 0; mi < 4; mi++) {
#pragma unroll
                for (int ni = 0; ni < 4; ni++) {
                    int m0 = bm + wm * 64 + mi * 16 + q;
                    int n0 = bn + wn * 32 + ni * 8 + r * 2;
                    float* a = acc[mi][ni];
                    float bv0 = bias[n0], bv1 = bias[n0 + 1];
                    float a0 = a[0] + bv0, a1 = a[1] + bv1;
                    float a2 = a[2] + bv0, a3 = a[3] + bv1;
                    float p0 = __shfl_xor_sync(0xFFFFFFFFu, a0, 1);
                    float p1 = __shfl_xor_sync(0xFFFFFFFFu, a1, 1);
                    float p2 = __shfl_xor_sync(0xFFFFFFFFu, a2, 1);
                    float p3 = __shfl_xor_sync(0xFFFFFFFFu, a3, 1);
                    if ((r & 1) == 0) {
                        int n = n0 >> 2;
#pragma unroll
                        for (int rr = 0; rr < 2; rr++) {
                            int m = m0 + rr * 8;
                            float gi = rr ? a2 : a0;
                            float gf = rr ? a3 : a1;
                            float gg = rr ? p2 : p0;
                            float go = rr ? p3 : p1;
                            float cn;
                            if (t == 0) {
                                cn = sigm(gi) * tanhf(gg);
                            } else {
                                float cold = __ldcg(cst + (size_t)m * HH + n);
                                cn = sigm(gf) * cold + sigm(gi) * tanhf(gg);
                            }
                            __stcg(cst + (size_t)m * HH + n, cn);
                            float h = sigm(go) * tanhf(cn);
                            bf16 hh, hl;
                            split1(h, hh, hl);
                            Chi[(size_t)m * HH + n] = hh;
                            Clo[(size_t)m * HH + n] = hl;
                        }
                    }
                }
            }
            __threadfence();
            __syncthreads();
            if (tid == 0) {
                int batch = fcb;
                if (atomicAdd(&done[batch], 1) == TPB - 1) {
                    if (l < LAYERS - 1) {
                        if (atomicSub(&dep[batch + 40], 1) == 1) {
                            int p = atomicAdd(&sched[1241], 1);
                            __stcg(&rq[p], batch + 40);
                        }
                    }
                    if (t < WW - 1) {
                        if (atomicSub(&dep[batch + 4], 1) == 1) {
                            int p = atomicAdd(&sched[1241], 1);
                            __stcg(&rq[p], batch + 4);
                        }
                    }
                }
            }
        }
    }
}

// ---------------- prep (merged): weight splits + bias + scheduler init -------
__global__ void prep_all(const float* __restrict__ fc0_w, const float* __restrict__ fc1_w,
                         const float* __restrict__ wih, const float* __restrict__ whh,
                         const float* __restrict__ bih, const float* __restrict__ bhh,
                         bf16* __restrict__ f0h, bf16* __restrict__ f0l,
                         bf16* __restrict__ f1h, bf16* __restrict__ f1l,
                         bf16* __restrict__ ihh, bf16* __restrict__ ihl,
                         bf16* __restrict__ hhh, bf16* __restrict__ hhl,
                         float* __restrict__ bc, int* __restrict__ sched)
{
    int i = blockIdx.x * blockDim.x + threadIdx.x;
    const int NA = HH * HH;
    const int NB = NA + HH * KFC1;
    const int NP = 2 * LAYERS * G4H * HH;
    if (i < NA) { split1(fc0_w[i], f0h[i], f0l[i]); return; }
    if (i < NB) { int j = i - NA; split1(fc1_w[j], f1h[j], f1l[j]); return; }
    int i2 = i - NB;
    if (i2 < NP) {
        int sel = i2 >= NP / 2;
        int ii = sel ? i2 - NP / 2 : i2;
        int k = ii % HH;
        int j = (ii / HH) % G4H;
        int l = ii / (HH * G4H);
        int n = j >> 2, g = j & 3;
        const float* src = sel ? whh : wih;
        float v = src[(size_t)l * G4H * HH + (size_t)(g * HH + n) * HH + k];
        if (sel) split1(v, hhh[ii], hhl[ii]);
        else     split1(v, ihh[ii], ihl[ii]);
        return;
    }
    int i3 = i2 - NP;
    if (i3 < LAYERS * G4H) {
        int j = i3 % G4H;
        int l = i3 / G4H;
        int n = j >> 2, g = j & 3;
        bc[i3] = bih[l * G4H + g * HH + n] + bhh[l * G4H + g * HH + n];
        return;
    }
    int i4 = i3 - LAYERS * G4H;
    if (i4 < 1280) {
        if (i4 < 440) sched[i4] = 0;                       // done (LSTM + fc0)
        else if (i4 < 840) {                               // dep[400]
            int b = i4 - 440;
            int tt = (b % 40) >> 2;
            sched[i4] = 1 + (tt > 0 ? 1 : 0);              // input-dep + h-dep
        } else if (i4 < 1240) sched[i4] = -1;              // readyq
        else sched[i4] = 0;                                // ticket, qtail
    }
}

// (B,W,H) fp32 -> (W*B, H) split bf16
__global__ void transpose_split(const float* __restrict__ src,
                                bf16* __restrict__ hi, bf16* __restrict__ lo)
{
    int i = blockIdx.x * blockDim.x + threadIdx.x;
    if (i >= TB * HH) return;
    int k = i % HH;
    int row = i / HH;
    int t = row / BB, b = row % BB;
    split1(src[((size_t)b * WW + t) * HH + k], hi[i], lo[i]);
}

// (W,B,H) split -> (B, W*H) split
__global__ void pack_split(const bf16* __restrict__ xhi, const bf16* __restrict__ xlo,
                           bf16* __restrict__ chi, bf16* __restrict__ clo)
{
    int i = blockIdx.x * blockDim.x + threadIdx.x;
    if (i >= BB * KFC1) return;
    int b = i / KFC1;
    int tk = i % KFC1;
    int t = tk / HH, k = tk % HH;
    size_t s = ((size_t)t * BB + b) * HH + k;
    chi[i] = xhi[s];
    clo[i] = xlo[s];
}

__global__ void reduce_fc1(const float* __restrict__ part, const float* __restrict__ b,
                           float* __restrict__ out)
{
    int i = blockIdx.x * blockDim.x + threadIdx.x;
    if (i >= BB * HH) return;
    float s = b[i % HH];
#pragma unroll
    for (int z = 0; z < SPLITK; z++) s += part[(size_t)z * BB * HH + i];
    out[i] = s;
}

// ---------------- host -------------------------------------------------------
extern "C" void kernel_launch(void* const* d_in, const int* in_sizes, int n_in,
                              void* d_out, int out_size)
{
    const float* xpos  = (const float*)d_in[0];
    const float* fc0_w = (const float*)d_in[1];
    const float* fc0_b = (const float*)d_in[2];
    const float* w_ih  = (const float*)d_in[3];
    const float* w_hh  = (const float*)d_in[4];
    const float* b_ih  = (const float*)d_in[5];
    const float* b_hh  = (const float*)d_in[6];
    const float* fc1_w = (const float*)d_in[7];
    const float* fc1_b = (const float*)d_in[8];
    float* out = (float*)d_out;

    bf16 *xhi, *xlo, *xcathi, *xcatlo;
    bf16 *fc0whi, *fc0wlo, *fc1whi, *fc1wlo, *wihhi, *wihlo, *whhhi, *whhlo;
    float *c, *bcomb, *part;
    int* sched;
    cudaGetSymbolAddress((void**)&xhi,   g_xhi);
    cudaGetSymbolAddress((void**)&xlo,   g_xlo);
    cudaGetSymbolAddress((void**)&xcathi, g_xcathi);
    cudaGetSymbolAddress((void**)&xcatlo, g_xcatlo);
    cudaGetSymbolAddress((void**)&fc0whi, g_fc0whi);
    cudaGetSymbolAddress((void**)&fc0wlo, g_fc0wlo);
    cudaGetSymbolAddress((void**)&fc1whi, g_fc1whi);
    cudaGetSymbolAddress((void**)&fc1wlo, g_fc1wlo);
    cudaGetSymbolAddress((void**)&wihhi, g_wihhi);
    cudaGetSymbolAddress((void**)&wihlo, g_wihlo);
    cudaGetSymbolAddress((void**)&whhhi, g_whhhi);
    cudaGetSymbolAddress((void**)&whhlo, g_whhlo);
    cudaGetSymbolAddress((void**)&c,     g_c);
    cudaGetSymbolAddress((void**)&bcomb, g_bcomb);
    cudaGetSymbolAddress((void**)&part,  g_part);
    cudaGetSymbolAddress((void**)&sched, g_sched);

    static bool once = false;
    if (!once) {
        cudaFuncSetAttribute(gemm_bf16<4>, cudaFuncAttributeMaxDynamicSharedMemorySize, SMEM_BYTES);
        cudaFuncSetAttribute(mega_kernel,  cudaFuncAttributeMaxDynamicSharedMemorySize, SMEM_BYTES);
        once = true;
    }

    const int EL = 256;

    // launch 0: input transpose/split
    transpose_split<<<(TB * HH + EL - 1) / EL, EL>>>(xpos, xcathi, xcatlo);

    // launch 1: merged prep (weights, biases, scheduler init)
    {
        int n = HH * HH + HH * KFC1 + 2 * LAYERS * G4H * HH + LAYERS * G4H + 1280;
        prep_all<<<(n + EL - 1) / EL, EL>>>(fc0_w, fc1_w, w_ih, w_hh, b_ih, b_hh,
                                            fc0whi, fc0wlo, fc1whi, fc1wlo,
                                            wihhi, wihlo, whhhi, whhlo, bcomb, sched);
    }

    // launch 2: dataflow mega kernel (fc0 + all layers/steps)
    mega_kernel<<<LGRID, 256, SMEM_BYTES>>>(
        xhi, xlo, xcathi, xcatlo, fc0whi, fc0wlo, fc0_b,
        wihhi, wihlo, whhhi, whhlo, bcomb, c, sched);

    // x[10] -> packed fc1 input
    pack_split<<<(BB * KFC1 + EL - 1) / EL, EL>>>(
        xhi + (size_t)10 * TB * HH, xlo + (size_t)10 * TB * HH, xcathi, xcatlo);

    // fc1 split-K partials + reduce
    gemm_bf16<4><<<dim3(HH / 128, BB / 128, SPLITK), 256, SMEM_BYTES>>>(
        xcathi, xcatlo, fc1whi, fc1wlo,
        part, BB, HH, KFC1, SPLITK);
    reduce_fc1<<<(BB * HH + EL - 1) / EL, EL>>>(part, fc1_b, out);
}